// round 7
// baseline (speedup 1.0000x reference)
#include <cuda_runtime.h>
#include <cuda_fp16.h>
#include <cstdint>
#include <cstddef>

// Problem dims (fixed by the dataset)
#define M_DIM   8192      // 4*2048 rows of x
#define IN_DIM  4096      // K of main GEMM
#define OUT_DIM 11008     // N of main GEMM
#define RANK_   192

// ---------------------------------------------------------------------------
// Scratch (static __device__ arrays — allocation-free per harness rules)
// ---------------------------------------------------------------------------
__device__ __align__(256) float  g_w [(size_t)OUT_DIM * IN_DIM];  // weight+delta fp32
__device__ __align__(256) __half g_xh[(size_t)M_DIM  * IN_DIM];   // x as fp16
__device__ __align__(256) __half g_wh[(size_t)OUT_DIM * IN_DIM];  // quantized w as fp16

__device__ __forceinline__ float to_tf32(float x) {
    uint32_t u;
    asm("cvt.rna.tf32.f32 %0, %1;" : "=r"(u) : "f"(x));
    return __uint_as_float(u);
}

// ---------------------------------------------------------------------------
// x -> fp16
// ---------------------------------------------------------------------------
__global__ void cvt_half_kernel(const float* __restrict__ in,
                                __half* __restrict__ out, int n4) {
    int i = blockIdx.x * 256 + threadIdx.x;
    if (i < n4) {
        float4 v = reinterpret_cast<const float4*>(in)[i];
        __half2 h0 = __floats2half2_rn(v.x, v.y);
        __half2 h1 = __floats2half2_rn(v.z, v.w);
        uint2 p;
        p.x = *reinterpret_cast<uint32_t*>(&h0);
        p.y = *reinterpret_cast<uint32_t*>(&h1);
        reinterpret_cast<uint2*>(out)[i] = p;
    }
}

// ---------------------------------------------------------------------------
// Row-wise 4-bit asymmetric fake quant: read fp32 g_w, emit fp16 g_wh.
// ---------------------------------------------------------------------------
__global__ void quant_kernel(const float* __restrict__ w, __half* __restrict__ wh) {
    const int row = blockIdx.x;
    const float* p = w + (size_t)row * IN_DIM;
    __half* po = wh + (size_t)row * IN_DIM;
    const int tid = threadIdx.x;

    float mn = 0.0f, mx = 0.0f;   // init 0 implements min/max-with-0 clamp
    #pragma unroll
    for (int i = tid; i < IN_DIM / 4; i += 256) {
        float4 v = reinterpret_cast<const float4*>(p)[i];
        mn = fminf(mn, fminf(fminf(v.x, v.y), fminf(v.z, v.w)));
        mx = fmaxf(mx, fmaxf(fmaxf(v.x, v.y), fmaxf(v.z, v.w)));
    }
    #pragma unroll
    for (int o = 16; o; o >>= 1) {
        mn = fminf(mn, __shfl_xor_sync(0xffffffffu, mn, o));
        mx = fmaxf(mx, __shfl_xor_sync(0xffffffffu, mx, o));
    }
    __shared__ float smn[8], smx[8];
    __shared__ float s_scale, s_zero;
    const int warp = tid >> 5, lane = tid & 31;
    if (lane == 0) { smn[warp] = mn; smx[warp] = mx; }
    __syncthreads();
    if (tid == 0) {
        float a = smn[0], b = smx[0];
        #pragma unroll
        for (int i = 1; i < 8; i++) { a = fminf(a, smn[i]); b = fmaxf(b, smx[i]); }
        float sc = fmaxf((b - a) / 15.0f, 1e-8f);
        s_scale = sc;
        s_zero  = rintf(-a / sc);
    }
    __syncthreads();
    const float sc = s_scale, z = s_zero;

    #pragma unroll
    for (int i = tid; i < IN_DIM / 4; i += 256) {
        float4 v = reinterpret_cast<const float4*>(p)[i];
        float q0 = (fminf(fmaxf(rintf(v.x / sc) + z, 0.0f), 15.0f) - z) * sc;
        float q1 = (fminf(fmaxf(rintf(v.y / sc) + z, 0.0f), 15.0f) - z) * sc;
        float q2 = (fminf(fmaxf(rintf(v.z / sc) + z, 0.0f), 15.0f) - z) * sc;
        float q3 = (fminf(fmaxf(rintf(v.w / sc) + z, 0.0f), 15.0f) - z) * sc;
        __half2 h0 = __floats2half2_rn(q0, q1);
        __half2 h1 = __floats2half2_rn(q2, q3);
        uint2 pk;
        pk.x = *reinterpret_cast<uint32_t*>(&h0);
        pk.y = *reinterpret_cast<uint32_t*>(&h1);
        reinterpret_cast<uint2*>(po)[i] = pk;
    }
}

// ---------------------------------------------------------------------------
// FUSED delta GEMM (single pass, fp32-equivalent via 3xTF32 in-register):
//   D[M,N] = C[M,N] + A[M,K] @ B[K,N],  A=Bd fp32, B=Bu fp32, C=weight.
// ---------------------------------------------------------------------------
#define BK       32
#define ASTRIDE  36
#define BSTRIDE_KN 136
#define ASZ (128 * ASTRIDE)
#define BSZ (128 * ASTRIDE)
#define SMEM_BYTES ((2 * ASZ + 2 * BSZ) * 4)   // 73728

__device__ __forceinline__ void cp16(uint32_t s, const void* g) {
    asm volatile("cp.async.cg.shared.global [%0], [%1], 16;\n" :: "r"(s), "l"(g));
}

__device__ __forceinline__ void mma_tf32(float* d, uint32_t a0, uint32_t a1,
                                         uint32_t a2, uint32_t a3,
                                         uint32_t b0, uint32_t b1) {
    asm volatile(
        "mma.sync.aligned.m16n8k8.row.col.f32.tf32.tf32.f32 "
        "{%0,%1,%2,%3}, {%4,%5,%6,%7}, {%8,%9}, {%0,%1,%2,%3};\n"
        : "+f"(d[0]), "+f"(d[1]), "+f"(d[2]), "+f"(d[3])
        : "r"(a0), "r"(a1), "r"(a2), "r"(a3), "r"(b0), "r"(b1));
}

__global__ __launch_bounds__(256, 2)
void gemm_delta_fused(const float* __restrict__ A, const float* __restrict__ B,
                      const float* __restrict__ C, float* __restrict__ D,
                      int M, int N, int K) {
    extern __shared__ float sm[];
    float* As = sm;
    float* Bs = sm + 2 * ASZ;

    const int tid  = threadIdx.x;
    const int lane = tid & 31, warp = tid >> 5;
    const int grp  = lane >> 2, tig = lane & 3;
    const int wm   = warp & 3,  wn  = warp >> 2;
    const int mBase = blockIdx.y * 128, nBase = blockIdx.x * 128;

    const uint32_t sA = (uint32_t)__cvta_generic_to_shared(As);
    const uint32_t sB = (uint32_t)__cvta_generic_to_shared(Bs);

    float acc[2][8][4];
    #pragma unroll
    for (int i = 0; i < 2; i++)
        #pragma unroll
        for (int j = 0; j < 8; j++)
            #pragma unroll
            for (int k = 0; k < 4; k++) acc[i][j][k] = 0.0f;

    const int KT = K / BK;   // 6

    auto issue_tile = [&](int kt, int buf) {
        const float* ga = A + (size_t)mBase * K + (size_t)kt * BK;
        #pragma unroll
        for (int i = 0; i < 4; i++) {
            int idx = tid + i * 256;
            int r = idx >> 3, c = (idx & 7) << 2;
            cp16(sA + (uint32_t)((buf * ASZ + r * ASTRIDE + c) << 2),
                 ga + (size_t)r * K + c);
        }
        const float* gb = B + (size_t)(kt * BK) * N + nBase;
        #pragma unroll
        for (int i = 0; i < 4; i++) {
            int idx = tid + i * 256;
            int k = idx >> 5, c = (idx & 31) << 2;
            cp16(sB + (uint32_t)((buf * BSZ + k * BSTRIDE_KN + c) << 2),
                 gb + (size_t)k * N + c);
        }
        asm volatile("cp.async.commit_group;\n");
    };

    issue_tile(0, 0);

    for (int kt = 0; kt < KT; ++kt) {
        const int buf = kt & 1;
        if (kt + 1 < KT) {
            issue_tile(kt + 1, buf ^ 1);
            asm volatile("cp.async.wait_group 1;\n");
        } else {
            asm volatile("cp.async.wait_group 0;\n");
        }
        __syncthreads();

        const float* a = As + buf * ASZ;
        const float* b = Bs + buf * BSZ;

        #pragma unroll
        for (int ks = 0; ks < 4; ++ks) {
            const int kb = ks * 8;
            uint32_t ah[2][4], al[2][4];
            #pragma unroll
            for (int mi = 0; mi < 2; ++mi) {
                const int m = wm * 32 + mi * 16 + grp;
                float v0 = a[m       * ASTRIDE + kb + tig];
                float v1 = a[(m + 8) * ASTRIDE + kb + tig];
                float v2 = a[m       * ASTRIDE + kb + 4 + tig];
                float v3 = a[(m + 8) * ASTRIDE + kb + 4 + tig];
                float h0 = to_tf32(v0), h1 = to_tf32(v1);
                float h2 = to_tf32(v2), h3 = to_tf32(v3);
                ah[mi][0] = __float_as_uint(h0); al[mi][0] = __float_as_uint(to_tf32(v0 - h0));
                ah[mi][1] = __float_as_uint(h1); al[mi][1] = __float_as_uint(to_tf32(v1 - h1));
                ah[mi][2] = __float_as_uint(h2); al[mi][2] = __float_as_uint(to_tf32(v2 - h2));
                ah[mi][3] = __float_as_uint(h3); al[mi][3] = __float_as_uint(to_tf32(v3 - h3));
            }
            #pragma unroll
            for (int nh = 0; nh < 2; ++nh) {
                uint32_t bh0[4], bl0[4], bh1[4], bl1[4];
                #pragma unroll
                for (int nj = 0; nj < 4; ++nj) {
                    const int n = wn * 64 + (nh * 4 + nj) * 8 + grp;
                    float v0 = b[(kb + tig)     * BSTRIDE_KN + n];
                    float v1 = b[(kb + 4 + tig) * BSTRIDE_KN + n];
                    float h0 = to_tf32(v0), h1 = to_tf32(v1);
                    bh0[nj] = __float_as_uint(h0); bl0[nj] = __float_as_uint(to_tf32(v0 - h0));
                    bh1[nj] = __float_as_uint(h1); bl1[nj] = __float_as_uint(to_tf32(v1 - h1));
                }
                #pragma unroll
                for (int mi = 0; mi < 2; ++mi) {
                    #pragma unroll
                    for (int nj = 0; nj < 4; ++nj) {
                        float* d = acc[mi][nh * 4 + nj];
                        mma_tf32(d, ah[mi][0], ah[mi][1], ah[mi][2], ah[mi][3],
                                 bh0[nj], bh1[nj]);
                        mma_tf32(d, ah[mi][0], ah[mi][1], ah[mi][2], ah[mi][3],
                                 bl0[nj], bl1[nj]);
                        mma_tf32(d, al[mi][0], al[mi][1], al[mi][2], al[mi][3],
                                 bh0[nj], bh1[nj]);
                    }
                }
            }
        }
        __syncthreads();
    }

    #pragma unroll
    for (int mi = 0; mi < 2; ++mi) {
        #pragma unroll
        for (int ni = 0; ni < 8; ++ni) {
            const int r0 = mBase + wm * 32 + mi * 16 + grp;
            const int cc = nBase + wn * 64 + ni * 8 + 2 * tig;
            float2 add0 = *reinterpret_cast<const float2*>(&C[(size_t)r0 * N + cc]);
            float2 add1 = *reinterpret_cast<const float2*>(&C[(size_t)(r0 + 8) * N + cc]);
            float2 o0 = make_float2(acc[mi][ni][0] + add0.x, acc[mi][ni][1] + add0.y);
            float2 o1 = make_float2(acc[mi][ni][2] + add1.x, acc[mi][ni][3] + add1.y);
            *reinterpret_cast<float2*>(&D[(size_t)r0 * N + cc])       = o0;
            *reinterpret_cast<float2*>(&D[(size_t)(r0 + 8) * N + cc]) = o1;
        }
    }
}

// ---------------------------------------------------------------------------
// Main GEMM: out[8192,11008] = xh[8192,4096] @ wh[11008,4096]^T + bias
// fp16 mma.sync.m16n8k16, ldmatrix, CTA 128x256, 4-stage cp.async.
// R7: 512 threads (16 warps = 4/SMSP) for latency hiding; warp tile 32x64.
// ---------------------------------------------------------------------------
#define BM 128
#define BN 256
#define BKH 32
#define ROWB 80
#define A_BYTES (BM * ROWB)
#define B_BYTES (BN * ROWB)
#define STAGE_BYTES (A_BYTES + B_BYTES)
#define NSTAGE 4
#define MAIN_SMEM (NSTAGE * STAGE_BYTES)
#define KTILES (IN_DIM / BKH)

__device__ __forceinline__ void ldsm_x4(uint32_t* r, uint32_t addr) {
    asm volatile("ldmatrix.sync.aligned.m8n8.x4.shared.b16 {%0,%1,%2,%3}, [%4];"
                 : "=r"(r[0]), "=r"(r[1]), "=r"(r[2]), "=r"(r[3]) : "r"(addr));
}

__device__ __forceinline__ void mma_f16(float* d, const uint32_t* a,
                                        uint32_t b0, uint32_t b1) {
    asm volatile(
        "mma.sync.aligned.m16n8k16.row.col.f32.f16.f16.f32 "
        "{%0,%1,%2,%3}, {%4,%5,%6,%7}, {%8,%9}, {%0,%1,%2,%3};\n"
        : "+f"(d[0]), "+f"(d[1]), "+f"(d[2]), "+f"(d[3])
        : "r"(a[0]), "r"(a[1]), "r"(a[2]), "r"(a[3]), "r"(b0), "r"(b1));
}

__global__ __launch_bounds__(512, 1)
void gemm_main_fp16(const __half* __restrict__ xh, const __half* __restrict__ wh,
                    const float* __restrict__ bias, float* __restrict__ out) {
    extern __shared__ __align__(128) unsigned char smem[];
    const uint32_t sb = (uint32_t)__cvta_generic_to_shared(smem);
    const int tid = threadIdx.x, warp = tid >> 5, lane = tid & 31;
    const int wm = warp & 3, wn = warp >> 2;   // 4M x 4N warps, warp tile 32x64

    int g = blockIdx.x, mTile, nTile;
    if (g < 2560) { int grp = g >> 9, loc = g & 511; nTile = grp * 8 + (loc & 7); mTile = loc >> 3; }
    else          { int loc = g - 2560; nTile = 40 + loc % 3; mTile = loc / 3; }
    const int mBase = mTile * BM, nBase = nTile * BN;

    // cp.async: A = 128 rows x 4 chunks = 512 (1/thread); B = 1024 (2/thread)
    const __half* gA0;
    uint32_t sAoff0;
    {
        int r = tid >> 2, s = tid & 3;
        gA0 = xh + (size_t)(mBase + r) * IN_DIM + s * 8;
        sAoff0 = r * ROWB + s * 16;
    }
    const __half* gB[2];
    uint32_t sBoff[2];
    #pragma unroll
    for (int i = 0; i < 2; i++) {
        int c = tid + i * 512;
        int r = c >> 2, s = c & 3;
        gB[i] = wh + (size_t)(nBase + r) * IN_DIM + s * 8;
        sBoff[i] = A_BYTES + r * ROWB + s * 16;
    }

    auto issue = [&](int kt) {
        const uint32_t base = sb + (uint32_t)(kt & (NSTAGE - 1)) * STAGE_BYTES;
        const int koff = kt * BKH;
        cp16(base + sAoff0, gA0 + koff);
        #pragma unroll
        for (int i = 0; i < 2; i++) cp16(base + sBoff[i], gB[i] + koff);
        asm volatile("cp.async.commit_group;\n");
    };

    const int mat = lane >> 3, mrow = lane & 7;
    // A warp tile 32 rows: mi in {0,1}; mats: (mat&1)->m+8, (mat>>1)->k half
    const uint32_t aAddr0 = (uint32_t)(wm * 32 + ((mat & 1) << 3) + mrow) * ROWB
                          + ((mat >> 1) << 4);
    // B warp tile 64 rows: nj in {0..3}; mats: (mat>>1)->n+8, (mat&1)->k half
    const uint32_t bAddr0 = A_BYTES
                          + (uint32_t)(wn * 64 + ((mat >> 1) << 3) + mrow) * ROWB
                          + ((mat & 1) << 4);

    float acc[2][8][4];
    #pragma unroll
    for (int i = 0; i < 2; i++)
        #pragma unroll
        for (int j = 0; j < 8; j++)
            #pragma unroll
            for (int k = 0; k < 4; k++) acc[i][j][k] = 0.0f;

    issue(0); issue(1); issue(2);

    for (int kt = 0; kt < KTILES; ++kt) {
        if (kt < KTILES - 2)       { asm volatile("cp.async.wait_group 2;\n"); }
        else if (kt == KTILES - 2) { asm volatile("cp.async.wait_group 1;\n"); }
        else                       { asm volatile("cp.async.wait_group 0;\n"); }
        __syncthreads();
        if (kt + 3 < KTILES) issue(kt + 3);

        const uint32_t base = sb + (uint32_t)(kt & (NSTAGE - 1)) * STAGE_BYTES;

        #pragma unroll
        for (int kk = 0; kk < 2; ++kk) {
            uint32_t af[2][4], bf[4][4];
            #pragma unroll
            for (int mi = 0; mi < 2; ++mi)
                ldsm_x4(af[mi], base + aAddr0 + mi * (16 * ROWB) + kk * 32);
            #pragma unroll
            for (int nj = 0; nj < 4; ++nj)
                ldsm_x4(bf[nj], base + bAddr0 + nj * (16 * ROWB) + kk * 32);
            #pragma unroll
            for (int mi = 0; mi < 2; ++mi) {
                #pragma unroll
                for (int nj = 0; nj < 4; ++nj) {
                    mma_f16(acc[mi][nj * 2],     af[mi], bf[nj][0], bf[nj][1]);
                    mma_f16(acc[mi][nj * 2 + 1], af[mi], bf[nj][2], bf[nj][3]);
                }
            }
        }
    }

    // Epilogue: warp tile 32x64 at (wm*32, wn*64)
    const int mRow = mBase + wm * 32 + (lane >> 2);
    const int nCol = nBase + wn * 64 + ((lane & 3) << 1);
    #pragma unroll
    for (int mi = 0; mi < 2; ++mi) {
        const int m0 = mRow + mi * 16;
        #pragma unroll
        for (int njh = 0; njh < 8; ++njh) {
            const int n = nCol + njh * 8;
            float2 b2 = *reinterpret_cast<const float2*>(&bias[n]);
            float2 o0 = make_float2(acc[mi][njh][0] + b2.x, acc[mi][njh][1] + b2.y);
            float2 o1 = make_float2(acc[mi][njh][2] + b2.x, acc[mi][njh][3] + b2.y);
            *reinterpret_cast<float2*>(&out[(size_t)m0 * OUT_DIM + n])       = o0;
            *reinterpret_cast<float2*>(&out[(size_t)(m0 + 8) * OUT_DIM + n]) = o1;
        }
    }
}

// ---------------------------------------------------------------------------
// Launch
// ---------------------------------------------------------------------------
extern "C" void kernel_launch(void* const* d_in, const int* in_sizes, int n_in,
                              void* d_out, int out_size) {
    const float *x = nullptr, *weight = nullptr, *Bd = nullptr,
                *Bu = nullptr, *bias = nullptr;
    for (int i = 0; i < n_in; i++) {
        switch (in_sizes[i]) {
            case 33554432: x      = (const float*)d_in[i]; break;  // 8192*4096
            case 45088768: weight = (const float*)d_in[i]; break;  // 11008*4096
            case 2113536:  Bd     = (const float*)d_in[i]; break;  // 11008*192
            case 786432:   Bu     = (const float*)d_in[i]; break;  // 192*4096
            case 11008:    bias   = (const float*)d_in[i]; break;
        }
    }
    if (!x && n_in > 0)      x      = (const float*)d_in[0];
    if (!weight && n_in > 1) weight = (const float*)d_in[1];
    if (!Bd && n_in > 2)     Bd     = (const float*)d_in[2];
    if (!Bu && n_in > 3)     Bu     = (const float*)d_in[3];
    if (!bias && n_in > 4)   bias   = (const float*)d_in[4];

    float *gw;
    __half *gxh, *gwh;
    cudaGetSymbolAddress((void**)&gw,  g_w);
    cudaGetSymbolAddress((void**)&gxh, g_xh);
    cudaGetSymbolAddress((void**)&gwh, g_wh);

    cudaFuncSetAttribute(gemm_delta_fused,
                         cudaFuncAttributeMaxDynamicSharedMemorySize, SMEM_BYTES);
    cudaFuncSetAttribute(gemm_main_fp16,
                         cudaFuncAttributeMaxDynamicSharedMemorySize, MAIN_SMEM);

    // 1) x -> fp16
    cvt_half_kernel<<<(33554432 / 4 + 255) / 256, 256>>>(x, gxh, 33554432 / 4);

    // 2) g_w = weight + Bd@Bu (single fused pass, fp32-equivalent 3xTF32)
    gemm_delta_fused<<<dim3(IN_DIM / 128, OUT_DIM / 128), 256, SMEM_BYTES>>>(
        Bd, Bu, weight, gw, OUT_DIM, IN_DIM, RANK_);

    // 3) fake-quant rows of g_w (fp32 decisions), emit fp16 g_wh
    quant_kernel<<<OUT_DIM, 256>>>(gw, gwh);

    // 4) out = xh @ wh^T + bias via fp16 m16n8k16 (16 warps/CTA)
    gemm_main_fp16<<<2752, 512, MAIN_SMEM>>>(gxh, gwh, bias, (float*)d_out);
}

// round 8
// speedup vs baseline: 1.1171x; 1.1171x over previous
#include <cuda_runtime.h>
#include <cuda_fp16.h>
#include <cstdint>
#include <cstddef>

// Problem dims (fixed by the dataset)
#define M_DIM   8192      // 4*2048 rows of x
#define IN_DIM  4096      // K of main GEMM
#define OUT_DIM 11008     // N of main GEMM
#define RANK_   192

// ---------------------------------------------------------------------------
// Scratch (static __device__ arrays — allocation-free per harness rules)
// ---------------------------------------------------------------------------
__device__ __align__(256) float  g_w [(size_t)OUT_DIM * IN_DIM];  // weight+delta fp32
__device__ __align__(256) __half g_xh[(size_t)M_DIM  * IN_DIM];   // x as fp16
__device__ __align__(256) __half g_wh[(size_t)OUT_DIM * IN_DIM];  // quantized w as fp16

__device__ __forceinline__ float to_tf32(float x) {
    uint32_t u;
    asm("cvt.rna.tf32.f32 %0, %1;" : "=r"(u) : "f"(x));
    return __uint_as_float(u);
}

// ---------------------------------------------------------------------------
// x -> fp16
// ---------------------------------------------------------------------------
__global__ void cvt_half_kernel(const float* __restrict__ in,
                                __half* __restrict__ out, int n4) {
    int i = blockIdx.x * 256 + threadIdx.x;
    if (i < n4) {
        float4 v = reinterpret_cast<const float4*>(in)[i];
        __half2 h0 = __floats2half2_rn(v.x, v.y);
        __half2 h1 = __floats2half2_rn(v.z, v.w);
        uint2 p;
        p.x = *reinterpret_cast<uint32_t*>(&h0);
        p.y = *reinterpret_cast<uint32_t*>(&h1);
        reinterpret_cast<uint2*>(out)[i] = p;
    }
}

// ---------------------------------------------------------------------------
// Row-wise 4-bit asymmetric fake quant: read fp32 g_w, emit fp16 g_wh.
// ---------------------------------------------------------------------------
__global__ void quant_kernel(const float* __restrict__ w, __half* __restrict__ wh) {
    const int row = blockIdx.x;
    const float* p = w + (size_t)row * IN_DIM;
    __half* po = wh + (size_t)row * IN_DIM;
    const int tid = threadIdx.x;

    float mn = 0.0f, mx = 0.0f;   // init 0 implements min/max-with-0 clamp
    #pragma unroll
    for (int i = tid; i < IN_DIM / 4; i += 256) {
        float4 v = reinterpret_cast<const float4*>(p)[i];
        mn = fminf(mn, fminf(fminf(v.x, v.y), fminf(v.z, v.w)));
        mx = fmaxf(mx, fmaxf(fmaxf(v.x, v.y), fmaxf(v.z, v.w)));
    }
    #pragma unroll
    for (int o = 16; o; o >>= 1) {
        mn = fminf(mn, __shfl_xor_sync(0xffffffffu, mn, o));
        mx = fmaxf(mx, __shfl_xor_sync(0xffffffffu, mx, o));
    }
    __shared__ float smn[8], smx[8];
    __shared__ float s_scale, s_zero;
    const int warp = tid >> 5, lane = tid & 31;
    if (lane == 0) { smn[warp] = mn; smx[warp] = mx; }
    __syncthreads();
    if (tid == 0) {
        float a = smn[0], b = smx[0];
        #pragma unroll
        for (int i = 1; i < 8; i++) { a = fminf(a, smn[i]); b = fmaxf(b, smx[i]); }
        float sc = fmaxf((b - a) / 15.0f, 1e-8f);
        s_scale = sc;
        s_zero  = rintf(-a / sc);
    }
    __syncthreads();
    const float sc = s_scale, z = s_zero;

    #pragma unroll
    for (int i = tid; i < IN_DIM / 4; i += 256) {
        float4 v = reinterpret_cast<const float4*>(p)[i];
        float q0 = (fminf(fmaxf(rintf(v.x / sc) + z, 0.0f), 15.0f) - z) * sc;
        float q1 = (fminf(fmaxf(rintf(v.y / sc) + z, 0.0f), 15.0f) - z) * sc;
        float q2 = (fminf(fmaxf(rintf(v.z / sc) + z, 0.0f), 15.0f) - z) * sc;
        float q3 = (fminf(fmaxf(rintf(v.w / sc) + z, 0.0f), 15.0f) - z) * sc;
        __half2 h0 = __floats2half2_rn(q0, q1);
        __half2 h1 = __floats2half2_rn(q2, q3);
        uint2 pk;
        pk.x = *reinterpret_cast<uint32_t*>(&h0);
        pk.y = *reinterpret_cast<uint32_t*>(&h1);
        reinterpret_cast<uint2*>(po)[i] = pk;
    }
}

// ---------------------------------------------------------------------------
// FUSED delta GEMM (single pass, fp32-equivalent via 3xTF32 in-register):
//   D[M,N] = C[M,N] + A[M,K] @ B[K,N],  A=Bd fp32, B=Bu fp32, C=weight.
// ---------------------------------------------------------------------------
#define BK       32
#define ASTRIDE  36
#define BSTRIDE_KN 136
#define ASZ (128 * ASTRIDE)
#define BSZ (128 * ASTRIDE)
#define SMEM_BYTES ((2 * ASZ + 2 * BSZ) * 4)   // 73728

__device__ __forceinline__ void cp16(uint32_t s, const void* g) {
    asm volatile("cp.async.cg.shared.global [%0], [%1], 16;\n" :: "r"(s), "l"(g));
}

__device__ __forceinline__ void mma_tf32(float* d, uint32_t a0, uint32_t a1,
                                         uint32_t a2, uint32_t a3,
                                         uint32_t b0, uint32_t b1) {
    asm volatile(
        "mma.sync.aligned.m16n8k8.row.col.f32.tf32.tf32.f32 "
        "{%0,%1,%2,%3}, {%4,%5,%6,%7}, {%8,%9}, {%0,%1,%2,%3};\n"
        : "+f"(d[0]), "+f"(d[1]), "+f"(d[2]), "+f"(d[3])
        : "r"(a0), "r"(a1), "r"(a2), "r"(a3), "r"(b0), "r"(b1));
}

__global__ __launch_bounds__(256, 2)
void gemm_delta_fused(const float* __restrict__ A, const float* __restrict__ B,
                      const float* __restrict__ C, float* __restrict__ D,
                      int M, int N, int K) {
    extern __shared__ float sm[];
    float* As = sm;
    float* Bs = sm + 2 * ASZ;

    const int tid  = threadIdx.x;
    const int lane = tid & 31, warp = tid >> 5;
    const int grp  = lane >> 2, tig = lane & 3;
    const int wm   = warp & 3,  wn  = warp >> 2;
    const int mBase = blockIdx.y * 128, nBase = blockIdx.x * 128;

    const uint32_t sA = (uint32_t)__cvta_generic_to_shared(As);
    const uint32_t sB = (uint32_t)__cvta_generic_to_shared(Bs);

    float acc[2][8][4];
    #pragma unroll
    for (int i = 0; i < 2; i++)
        #pragma unroll
        for (int j = 0; j < 8; j++)
            #pragma unroll
            for (int k = 0; k < 4; k++) acc[i][j][k] = 0.0f;

    const int KT = K / BK;   // 6

    auto issue_tile = [&](int kt, int buf) {
        const float* ga = A + (size_t)mBase * K + (size_t)kt * BK;
        #pragma unroll
        for (int i = 0; i < 4; i++) {
            int idx = tid + i * 256;
            int r = idx >> 3, c = (idx & 7) << 2;
            cp16(sA + (uint32_t)((buf * ASZ + r * ASTRIDE + c) << 2),
                 ga + (size_t)r * K + c);
        }
        const float* gb = B + (size_t)(kt * BK) * N + nBase;
        #pragma unroll
        for (int i = 0; i < 4; i++) {
            int idx = tid + i * 256;
            int k = idx >> 5, c = (idx & 31) << 2;
            cp16(sB + (uint32_t)((buf * BSZ + k * BSTRIDE_KN + c) << 2),
                 gb + (size_t)k * N + c);
        }
        asm volatile("cp.async.commit_group;\n");
    };

    issue_tile(0, 0);

    for (int kt = 0; kt < KT; ++kt) {
        const int buf = kt & 1;
        if (kt + 1 < KT) {
            issue_tile(kt + 1, buf ^ 1);
            asm volatile("cp.async.wait_group 1;\n");
        } else {
            asm volatile("cp.async.wait_group 0;\n");
        }
        __syncthreads();

        const float* a = As + buf * ASZ;
        const float* b = Bs + buf * BSZ;

        #pragma unroll
        for (int ks = 0; ks < 4; ++ks) {
            const int kb = ks * 8;
            uint32_t ah[2][4], al[2][4];
            #pragma unroll
            for (int mi = 0; mi < 2; ++mi) {
                const int m = wm * 32 + mi * 16 + grp;
                float v0 = a[m       * ASTRIDE + kb + tig];
                float v1 = a[(m + 8) * ASTRIDE + kb + tig];
                float v2 = a[m       * ASTRIDE + kb + 4 + tig];
                float v3 = a[(m + 8) * ASTRIDE + kb + 4 + tig];
                float h0 = to_tf32(v0), h1 = to_tf32(v1);
                float h2 = to_tf32(v2), h3 = to_tf32(v3);
                ah[mi][0] = __float_as_uint(h0); al[mi][0] = __float_as_uint(to_tf32(v0 - h0));
                ah[mi][1] = __float_as_uint(h1); al[mi][1] = __float_as_uint(to_tf32(v1 - h1));
                ah[mi][2] = __float_as_uint(h2); al[mi][2] = __float_as_uint(to_tf32(v2 - h2));
                ah[mi][3] = __float_as_uint(h3); al[mi][3] = __float_as_uint(to_tf32(v3 - h3));
            }
            #pragma unroll
            for (int nh = 0; nh < 2; ++nh) {
                uint32_t bh0[4], bl0[4], bh1[4], bl1[4];
                #pragma unroll
                for (int nj = 0; nj < 4; ++nj) {
                    const int n = wn * 64 + (nh * 4 + nj) * 8 + grp;
                    float v0 = b[(kb + tig)     * BSTRIDE_KN + n];
                    float v1 = b[(kb + 4 + tig) * BSTRIDE_KN + n];
                    float h0 = to_tf32(v0), h1 = to_tf32(v1);
                    bh0[nj] = __float_as_uint(h0); bl0[nj] = __float_as_uint(to_tf32(v0 - h0));
                    bh1[nj] = __float_as_uint(h1); bl1[nj] = __float_as_uint(to_tf32(v1 - h1));
                }
                #pragma unroll
                for (int mi = 0; mi < 2; ++mi) {
                    #pragma unroll
                    for (int nj = 0; nj < 4; ++nj) {
                        float* d = acc[mi][nh * 4 + nj];
                        mma_tf32(d, ah[mi][0], ah[mi][1], ah[mi][2], ah[mi][3],
                                 bh0[nj], bh1[nj]);
                        mma_tf32(d, ah[mi][0], ah[mi][1], ah[mi][2], ah[mi][3],
                                 bl0[nj], bl1[nj]);
                        mma_tf32(d, al[mi][0], al[mi][1], al[mi][2], al[mi][3],
                                 bh0[nj], bh1[nj]);
                    }
                }
            }
        }
        __syncthreads();
    }

    #pragma unroll
    for (int mi = 0; mi < 2; ++mi) {
        #pragma unroll
        for (int ni = 0; ni < 8; ++ni) {
            const int r0 = mBase + wm * 32 + mi * 16 + grp;
            const int cc = nBase + wn * 64 + ni * 8 + 2 * tig;
            float2 add0 = *reinterpret_cast<const float2*>(&C[(size_t)r0 * N + cc]);
            float2 add1 = *reinterpret_cast<const float2*>(&C[(size_t)(r0 + 8) * N + cc]);
            float2 o0 = make_float2(acc[mi][ni][0] + add0.x, acc[mi][ni][1] + add0.y);
            float2 o1 = make_float2(acc[mi][ni][2] + add1.x, acc[mi][ni][3] + add1.y);
            *reinterpret_cast<float2*>(&D[(size_t)r0 * N + cc])       = o0;
            *reinterpret_cast<float2*>(&D[(size_t)(r0 + 8) * N + cc]) = o1;
        }
    }
}

// ---------------------------------------------------------------------------
// Main GEMM: out[8192,11008] = xh[8192,4096] @ wh[11008,4096]^T + bias
// fp16 mma.sync.m16n8k16, ldmatrix, CTA tile 128x128, 256 threads,
// 2 CTAs/SM, 4-stage cp.async. 8 warps = 2M x 4N, warp tile 64x32.
// ---------------------------------------------------------------------------
#define BM 128
#define BN 128
#define BKH 32
#define ROWB 80
#define A_BYTES (BM * ROWB)              // 10240
#define B_BYTES (BN * ROWB)              // 10240
#define STAGE_BYTES (A_BYTES + B_BYTES)  // 20480
#define NSTAGE 4
#define MAIN_SMEM (NSTAGE * STAGE_BYTES) // 81920
#define KTILES (IN_DIM / BKH)            // 128
#define MTILES (M_DIM / BM)              // 64
#define NTILES (OUT_DIM / BN)            // 86

__device__ __forceinline__ void ldsm_x4(uint32_t* r, uint32_t addr) {
    asm volatile("ldmatrix.sync.aligned.m8n8.x4.shared.b16 {%0,%1,%2,%3}, [%4];"
                 : "=r"(r[0]), "=r"(r[1]), "=r"(r[2]), "=r"(r[3]) : "r"(addr));
}

__device__ __forceinline__ void mma_f16(float* d, const uint32_t* a,
                                        uint32_t b0, uint32_t b1) {
    asm volatile(
        "mma.sync.aligned.m16n8k16.row.col.f32.f16.f16.f32 "
        "{%0,%1,%2,%3}, {%4,%5,%6,%7}, {%8,%9}, {%0,%1,%2,%3};\n"
        : "+f"(d[0]), "+f"(d[1]), "+f"(d[2]), "+f"(d[3])
        : "r"(a[0]), "r"(a[1]), "r"(a[2]), "r"(a[3]), "r"(b0), "r"(b1));
}

__global__ __launch_bounds__(256, 2)
void gemm_main_fp16(const __half* __restrict__ xh, const __half* __restrict__ wh,
                    const float* __restrict__ bias, float* __restrict__ out) {
    extern __shared__ __align__(128) unsigned char smem[];
    const uint32_t sb = (uint32_t)__cvta_generic_to_shared(smem);
    const int tid = threadIdx.x, warp = tid >> 5, lane = tid & 31;
    const int wm = warp & 1, wn = warp >> 1;   // 2M x 4N warps, warp tile 64x32

    // Grid swizzle: 8-wide n-supercolumns (86 = 10*8 + 6).
    int g = blockIdx.x, mTile, nTile;
    if (g < MTILES * 80) { int sc = g >> 9, loc = g & 511; nTile = sc * 8 + (loc & 7); mTile = loc >> 3; }
    else                 { int loc = g - MTILES * 80; nTile = 80 + loc % 6; mTile = loc / 6; }
    const int mBase = mTile * BM, nBase = nTile * BN;

    // cp.async: A = 128 rows x 4 chunks = 512 (2/thread); B same.
    const __half* gA[2];
    uint32_t sAoff[2];
    const __half* gB[2];
    uint32_t sBoff[2];
    #pragma unroll
    for (int i = 0; i < 2; i++) {
        int c = tid + i * 256;
        int r = c >> 2, s = c & 3;
        gA[i] = xh + (size_t)(mBase + r) * IN_DIM + s * 8;
        sAoff[i] = r * ROWB + s * 16;
        gB[i] = wh + (size_t)(nBase + r) * IN_DIM + s * 8;
        sBoff[i] = A_BYTES + r * ROWB + s * 16;
    }

    auto issue = [&](int kt) {
        const uint32_t base = sb + (uint32_t)(kt & (NSTAGE - 1)) * STAGE_BYTES;
        const int koff = kt * BKH;
        #pragma unroll
        for (int i = 0; i < 2; i++) cp16(base + sAoff[i], gA[i] + koff);
        #pragma unroll
        for (int i = 0; i < 2; i++) cp16(base + sBoff[i], gB[i] + koff);
        asm volatile("cp.async.commit_group;\n");
    };

    const int mat = lane >> 3, mrow = lane & 7;
    // A warp tile 64 rows: mi in {0..3}; mats: (mat&1)->m+8, (mat>>1)->k half
    const uint32_t aAddr0 = (uint32_t)(wm * 64 + ((mat & 1) << 3) + mrow) * ROWB
                          + ((mat >> 1) << 4);
    // B warp tile 32 rows: nj in {0,1}; mats: (mat>>1)->n+8, (mat&1)->k half
    const uint32_t bAddr0 = A_BYTES
                          + (uint32_t)(wn * 32 + ((mat >> 1) << 3) + mrow) * ROWB
                          + ((mat & 1) << 4);

    float acc[4][4][4];
    #pragma unroll
    for (int i = 0; i < 4; i++)
        #pragma unroll
        for (int j = 0; j < 4; j++)
            #pragma unroll
            for (int k = 0; k < 4; k++) acc[i][j][k] = 0.0f;

    issue(0); issue(1); issue(2);

    for (int kt = 0; kt < KTILES; ++kt) {
        if (kt < KTILES - 2)       { asm volatile("cp.async.wait_group 2;\n"); }
        else if (kt == KTILES - 2) { asm volatile("cp.async.wait_group 1;\n"); }
        else                       { asm volatile("cp.async.wait_group 0;\n"); }
        __syncthreads();
        if (kt + 3 < KTILES) issue(kt + 3);

        const uint32_t base = sb + (uint32_t)(kt & (NSTAGE - 1)) * STAGE_BYTES;

        #pragma unroll
        for (int kk = 0; kk < 2; ++kk) {
            uint32_t af[4][4], bf[2][4];
            #pragma unroll
            for (int mi = 0; mi < 4; ++mi)
                ldsm_x4(af[mi], base + aAddr0 + mi * (16 * ROWB) + kk * 32);
            #pragma unroll
            for (int nj = 0; nj < 2; ++nj)
                ldsm_x4(bf[nj], base + bAddr0 + nj * (16 * ROWB) + kk * 32);
            #pragma unroll
            for (int mi = 0; mi < 4; ++mi) {
                #pragma unroll
                for (int nj = 0; nj < 2; ++nj) {
                    mma_f16(acc[mi][nj * 2],     af[mi], bf[nj][0], bf[nj][1]);
                    mma_f16(acc[mi][nj * 2 + 1], af[mi], bf[nj][2], bf[nj][3]);
                }
            }
        }
    }

    // Epilogue: warp tile 64x32 at (wm*64, wn*32)
    const int mRow = mBase + wm * 64 + (lane >> 2);
    const int nCol = nBase + wn * 32 + ((lane & 3) << 1);
    #pragma unroll
    for (int mi = 0; mi < 4; ++mi) {
        const int m0 = mRow + mi * 16;
        #pragma unroll
        for (int njh = 0; njh < 4; ++njh) {
            const int n = nCol + njh * 8;
            float2 b2 = *reinterpret_cast<const float2*>(&bias[n]);
            float2 o0 = make_float2(acc[mi][njh][0] + b2.x, acc[mi][njh][1] + b2.y);
            float2 o1 = make_float2(acc[mi][njh][2] + b2.x, acc[mi][njh][3] + b2.y);
            *reinterpret_cast<float2*>(&out[(size_t)m0 * OUT_DIM + n])       = o0;
            *reinterpret_cast<float2*>(&out[(size_t)(m0 + 8) * OUT_DIM + n]) = o1;
        }
    }
}

// ---------------------------------------------------------------------------
// Launch
// ---------------------------------------------------------------------------
extern "C" void kernel_launch(void* const* d_in, const int* in_sizes, int n_in,
                              void* d_out, int out_size) {
    const float *x = nullptr, *weight = nullptr, *Bd = nullptr,
                *Bu = nullptr, *bias = nullptr;
    for (int i = 0; i < n_in; i++) {
        switch (in_sizes[i]) {
            case 33554432: x      = (const float*)d_in[i]; break;  // 8192*4096
            case 45088768: weight = (const float*)d_in[i]; break;  // 11008*4096
            case 2113536:  Bd     = (const float*)d_in[i]; break;  // 11008*192
            case 786432:   Bu     = (const float*)d_in[i]; break;  // 192*4096
            case 11008:    bias   = (const float*)d_in[i]; break;
        }
    }
    if (!x && n_in > 0)      x      = (const float*)d_in[0];
    if (!weight && n_in > 1) weight = (const float*)d_in[1];
    if (!Bd && n_in > 2)     Bd     = (const float*)d_in[2];
    if (!Bu && n_in > 3)     Bu     = (const float*)d_in[3];
    if (!bias && n_in > 4)   bias   = (const float*)d_in[4];

    float *gw;
    __half *gxh, *gwh;
    cudaGetSymbolAddress((void**)&gw,  g_w);
    cudaGetSymbolAddress((void**)&gxh, g_xh);
    cudaGetSymbolAddress((void**)&gwh, g_wh);

    cudaFuncSetAttribute(gemm_delta_fused,
                         cudaFuncAttributeMaxDynamicSharedMemorySize, SMEM_BYTES);
    cudaFuncSetAttribute(gemm_main_fp16,
                         cudaFuncAttributeMaxDynamicSharedMemorySize, MAIN_SMEM);

    // 1) x -> fp16
    cvt_half_kernel<<<(33554432 / 4 + 255) / 256, 256>>>(x, gxh, 33554432 / 4);

    // 2) g_w = weight + Bd@Bu (single fused pass, fp32-equivalent 3xTF32)
    gemm_delta_fused<<<dim3(IN_DIM / 128, OUT_DIM / 128), 256, SMEM_BYTES>>>(
        Bd, Bu, weight, gw, OUT_DIM, IN_DIM, RANK_);

    // 3) fake-quant rows of g_w (fp32 decisions), emit fp16 g_wh
    quant_kernel<<<OUT_DIM, 256>>>(gw, gwh);

    // 4) out = xh @ wh^T + bias via fp16 m16n8k16 (128x128 tiles, 2 CTA/SM)
    gemm_main_fp16<<<MTILES * NTILES, 256, MAIN_SMEM>>>(gxh, gwh, bias,
                                                        (float*)d_out);
}

// round 9
// speedup vs baseline: 1.2522x; 1.1209x over previous
#include <cuda_runtime.h>
#include <cuda_fp16.h>
#include <cstdint>
#include <cstddef>

// Problem dims (fixed by the dataset)
#define M_DIM   8192      // 4*2048 rows of x
#define IN_DIM  4096      // K of main GEMM
#define OUT_DIM 11008     // N of main GEMM
#define RANK_   192

// ---------------------------------------------------------------------------
// Scratch (static __device__ arrays — allocation-free per harness rules)
// ---------------------------------------------------------------------------
__device__ __align__(256) float  g_w [(size_t)OUT_DIM * IN_DIM];  // weight+delta fp32
__device__ __align__(256) __half g_xh[(size_t)M_DIM  * IN_DIM];   // x as fp16
__device__ __align__(256) __half g_wh[(size_t)OUT_DIM * IN_DIM];  // quantized w as fp16

__device__ __forceinline__ float to_tf32(float x) {
    uint32_t u;
    asm("cvt.rna.tf32.f32 %0, %1;" : "=r"(u) : "f"(x));
    return __uint_as_float(u);
}

// ---------------------------------------------------------------------------
// x -> fp16
// ---------------------------------------------------------------------------
__global__ void cvt_half_kernel(const float* __restrict__ in,
                                __half* __restrict__ out, int n4) {
    int i = blockIdx.x * 256 + threadIdx.x;
    if (i < n4) {
        float4 v = reinterpret_cast<const float4*>(in)[i];
        __half2 h0 = __floats2half2_rn(v.x, v.y);
        __half2 h1 = __floats2half2_rn(v.z, v.w);
        uint2 p;
        p.x = *reinterpret_cast<uint32_t*>(&h0);
        p.y = *reinterpret_cast<uint32_t*>(&h1);
        reinterpret_cast<uint2*>(out)[i] = p;
    }
}

// ---------------------------------------------------------------------------
// Row-wise 4-bit asymmetric fake quant: read fp32 g_w, emit fp16 g_wh.
// ---------------------------------------------------------------------------
__global__ void quant_kernel(const float* __restrict__ w, __half* __restrict__ wh) {
    const int row = blockIdx.x;
    const float* p = w + (size_t)row * IN_DIM;
    __half* po = wh + (size_t)row * IN_DIM;
    const int tid = threadIdx.x;

    float mn = 0.0f, mx = 0.0f;   // init 0 implements min/max-with-0 clamp
    #pragma unroll
    for (int i = tid; i < IN_DIM / 4; i += 256) {
        float4 v = reinterpret_cast<const float4*>(p)[i];
        mn = fminf(mn, fminf(fminf(v.x, v.y), fminf(v.z, v.w)));
        mx = fmaxf(mx, fmaxf(fmaxf(v.x, v.y), fmaxf(v.z, v.w)));
    }
    #pragma unroll
    for (int o = 16; o; o >>= 1) {
        mn = fminf(mn, __shfl_xor_sync(0xffffffffu, mn, o));
        mx = fmaxf(mx, __shfl_xor_sync(0xffffffffu, mx, o));
    }
    __shared__ float smn[8], smx[8];
    __shared__ float s_scale, s_zero;
    const int warp = tid >> 5, lane = tid & 31;
    if (lane == 0) { smn[warp] = mn; smx[warp] = mx; }
    __syncthreads();
    if (tid == 0) {
        float a = smn[0], b = smx[0];
        #pragma unroll
        for (int i = 1; i < 8; i++) { a = fminf(a, smn[i]); b = fmaxf(b, smx[i]); }
        float sc = fmaxf((b - a) / 15.0f, 1e-8f);
        s_scale = sc;
        s_zero  = rintf(-a / sc);
    }
    __syncthreads();
    const float sc = s_scale, z = s_zero;

    #pragma unroll
    for (int i = tid; i < IN_DIM / 4; i += 256) {
        float4 v = reinterpret_cast<const float4*>(p)[i];
        float q0 = (fminf(fmaxf(rintf(v.x / sc) + z, 0.0f), 15.0f) - z) * sc;
        float q1 = (fminf(fmaxf(rintf(v.y / sc) + z, 0.0f), 15.0f) - z) * sc;
        float q2 = (fminf(fmaxf(rintf(v.z / sc) + z, 0.0f), 15.0f) - z) * sc;
        float q3 = (fminf(fmaxf(rintf(v.w / sc) + z, 0.0f), 15.0f) - z) * sc;
        __half2 h0 = __floats2half2_rn(q0, q1);
        __half2 h1 = __floats2half2_rn(q2, q3);
        uint2 pk;
        pk.x = *reinterpret_cast<uint32_t*>(&h0);
        pk.y = *reinterpret_cast<uint32_t*>(&h1);
        reinterpret_cast<uint2*>(po)[i] = pk;
    }
}

// ---------------------------------------------------------------------------
// FUSED delta GEMM (single pass, fp32-equivalent via 3xTF32 in-register):
//   D[M,N] = C[M,N] + A[M,K] @ B[K,N],  A=Bd fp32, B=Bu fp32, C=weight.
// ---------------------------------------------------------------------------
#define BK       32
#define ASTRIDE  36
#define BSTRIDE_KN 136
#define ASZ (128 * ASTRIDE)
#define BSZ (128 * ASTRIDE)
#define SMEM_BYTES ((2 * ASZ + 2 * BSZ) * 4)   // 73728

__device__ __forceinline__ void cp16(uint32_t s, const void* g) {
    asm volatile("cp.async.cg.shared.global [%0], [%1], 16;\n" :: "r"(s), "l"(g));
}

__device__ __forceinline__ void mma_tf32(float* d, uint32_t a0, uint32_t a1,
                                         uint32_t a2, uint32_t a3,
                                         uint32_t b0, uint32_t b1) {
    asm volatile(
        "mma.sync.aligned.m16n8k8.row.col.f32.tf32.tf32.f32 "
        "{%0,%1,%2,%3}, {%4,%5,%6,%7}, {%8,%9}, {%0,%1,%2,%3};\n"
        : "+f"(d[0]), "+f"(d[1]), "+f"(d[2]), "+f"(d[3])
        : "r"(a0), "r"(a1), "r"(a2), "r"(a3), "r"(b0), "r"(b1));
}

__global__ __launch_bounds__(256, 2)
void gemm_delta_fused(const float* __restrict__ A, const float* __restrict__ B,
                      const float* __restrict__ C, float* __restrict__ D,
                      int M, int N, int K) {
    extern __shared__ float sm[];
    float* As = sm;
    float* Bs = sm + 2 * ASZ;

    const int tid  = threadIdx.x;
    const int lane = tid & 31, warp = tid >> 5;
    const int grp  = lane >> 2, tig = lane & 3;
    const int wm   = warp & 3,  wn  = warp >> 2;
    const int mBase = blockIdx.y * 128, nBase = blockIdx.x * 128;

    const uint32_t sA = (uint32_t)__cvta_generic_to_shared(As);
    const uint32_t sB = (uint32_t)__cvta_generic_to_shared(Bs);

    float acc[2][8][4];
    #pragma unroll
    for (int i = 0; i < 2; i++)
        #pragma unroll
        for (int j = 0; j < 8; j++)
            #pragma unroll
            for (int k = 0; k < 4; k++) acc[i][j][k] = 0.0f;

    const int KT = K / BK;   // 6

    auto issue_tile = [&](int kt, int buf) {
        const float* ga = A + (size_t)mBase * K + (size_t)kt * BK;
        #pragma unroll
        for (int i = 0; i < 4; i++) {
            int idx = tid + i * 256;
            int r = idx >> 3, c = (idx & 7) << 2;
            cp16(sA + (uint32_t)((buf * ASZ + r * ASTRIDE + c) << 2),
                 ga + (size_t)r * K + c);
        }
        const float* gb = B + (size_t)(kt * BK) * N + nBase;
        #pragma unroll
        for (int i = 0; i < 4; i++) {
            int idx = tid + i * 256;
            int k = idx >> 5, c = (idx & 31) << 2;
            cp16(sB + (uint32_t)((buf * BSZ + k * BSTRIDE_KN + c) << 2),
                 gb + (size_t)k * N + c);
        }
        asm volatile("cp.async.commit_group;\n");
    };

    issue_tile(0, 0);

    for (int kt = 0; kt < KT; ++kt) {
        const int buf = kt & 1;
        if (kt + 1 < KT) {
            issue_tile(kt + 1, buf ^ 1);
            asm volatile("cp.async.wait_group 1;\n");
        } else {
            asm volatile("cp.async.wait_group 0;\n");
        }
        __syncthreads();

        const float* a = As + buf * ASZ;
        const float* b = Bs + buf * BSZ;

        #pragma unroll
        for (int ks = 0; ks < 4; ++ks) {
            const int kb = ks * 8;
            uint32_t ah[2][4], al[2][4];
            #pragma unroll
            for (int mi = 0; mi < 2; ++mi) {
                const int m = wm * 32 + mi * 16 + grp;
                float v0 = a[m       * ASTRIDE + kb + tig];
                float v1 = a[(m + 8) * ASTRIDE + kb + tig];
                float v2 = a[m       * ASTRIDE + kb + 4 + tig];
                float v3 = a[(m + 8) * ASTRIDE + kb + 4 + tig];
                float h0 = to_tf32(v0), h1 = to_tf32(v1);
                float h2 = to_tf32(v2), h3 = to_tf32(v3);
                ah[mi][0] = __float_as_uint(h0); al[mi][0] = __float_as_uint(to_tf32(v0 - h0));
                ah[mi][1] = __float_as_uint(h1); al[mi][1] = __float_as_uint(to_tf32(v1 - h1));
                ah[mi][2] = __float_as_uint(h2); al[mi][2] = __float_as_uint(to_tf32(v2 - h2));
                ah[mi][3] = __float_as_uint(h3); al[mi][3] = __float_as_uint(to_tf32(v3 - h3));
            }
            #pragma unroll
            for (int nh = 0; nh < 2; ++nh) {
                uint32_t bh0[4], bl0[4], bh1[4], bl1[4];
                #pragma unroll
                for (int nj = 0; nj < 4; ++nj) {
                    const int n = wn * 64 + (nh * 4 + nj) * 8 + grp;
                    float v0 = b[(kb + tig)     * BSTRIDE_KN + n];
                    float v1 = b[(kb + 4 + tig) * BSTRIDE_KN + n];
                    float h0 = to_tf32(v0), h1 = to_tf32(v1);
                    bh0[nj] = __float_as_uint(h0); bl0[nj] = __float_as_uint(to_tf32(v0 - h0));
                    bh1[nj] = __float_as_uint(h1); bl1[nj] = __float_as_uint(to_tf32(v1 - h1));
                }
                #pragma unroll
                for (int mi = 0; mi < 2; ++mi) {
                    #pragma unroll
                    for (int nj = 0; nj < 4; ++nj) {
                        float* d = acc[mi][nh * 4 + nj];
                        mma_tf32(d, ah[mi][0], ah[mi][1], ah[mi][2], ah[mi][3],
                                 bh0[nj], bh1[nj]);
                        mma_tf32(d, ah[mi][0], ah[mi][1], ah[mi][2], ah[mi][3],
                                 bl0[nj], bl1[nj]);
                        mma_tf32(d, al[mi][0], al[mi][1], al[mi][2], al[mi][3],
                                 bh0[nj], bh1[nj]);
                    }
                }
            }
        }
        __syncthreads();
    }

    #pragma unroll
    for (int mi = 0; mi < 2; ++mi) {
        #pragma unroll
        for (int ni = 0; ni < 8; ++ni) {
            const int r0 = mBase + wm * 32 + mi * 16 + grp;
            const int cc = nBase + wn * 64 + ni * 8 + 2 * tig;
            float2 add0 = *reinterpret_cast<const float2*>(&C[(size_t)r0 * N + cc]);
            float2 add1 = *reinterpret_cast<const float2*>(&C[(size_t)(r0 + 8) * N + cc]);
            float2 o0 = make_float2(acc[mi][ni][0] + add0.x, acc[mi][ni][1] + add0.y);
            float2 o1 = make_float2(acc[mi][ni][2] + add1.x, acc[mi][ni][3] + add1.y);
            *reinterpret_cast<float2*>(&D[(size_t)r0 * N + cc])       = o0;
            *reinterpret_cast<float2*>(&D[(size_t)(r0 + 8) * N + cc]) = o1;
        }
    }
}

// ---------------------------------------------------------------------------
// Main GEMM: out[8192,11008] = xh[8192,4096] @ wh[11008,4096]^T + bias
// fp16 mma.sync.m16n8k16, ldmatrix, CTA tile 128x128, 256 threads,
// 2 CTAs/SM. R9: K-chunk 64 halves (128B rows, ROWB=144), KTILES=64,
// 3-stage cp.async — half the barriers of R8.
// ---------------------------------------------------------------------------
#define BM 128
#define BN 128
#define BKH 64                            // halves of K per tile
#define ROWB 144                          // 128B data + 16B pad (conflict-free)
#define A_BYTES (BM * ROWB)               // 18432
#define B_BYTES (BN * ROWB)               // 18432
#define STAGE_BYTES (A_BYTES + B_BYTES)   // 36864
#define NSTAGE 3
#define MAIN_SMEM (NSTAGE * STAGE_BYTES)  // 110592
#define KTILES (IN_DIM / BKH)             // 64
#define MTILES (M_DIM / BM)               // 64
#define NTILES (OUT_DIM / BN)             // 86

__device__ __forceinline__ void ldsm_x4(uint32_t* r, uint32_t addr) {
    asm volatile("ldmatrix.sync.aligned.m8n8.x4.shared.b16 {%0,%1,%2,%3}, [%4];"
                 : "=r"(r[0]), "=r"(r[1]), "=r"(r[2]), "=r"(r[3]) : "r"(addr));
}

__device__ __forceinline__ void mma_f16(float* d, const uint32_t* a,
                                        uint32_t b0, uint32_t b1) {
    asm volatile(
        "mma.sync.aligned.m16n8k16.row.col.f32.f16.f16.f32 "
        "{%0,%1,%2,%3}, {%4,%5,%6,%7}, {%8,%9}, {%0,%1,%2,%3};\n"
        : "+f"(d[0]), "+f"(d[1]), "+f"(d[2]), "+f"(d[3])
        : "r"(a[0]), "r"(a[1]), "r"(a[2]), "r"(a[3]), "r"(b0), "r"(b1));
}

__global__ __launch_bounds__(256, 2)
void gemm_main_fp16(const __half* __restrict__ xh, const __half* __restrict__ wh,
                    const float* __restrict__ bias, float* __restrict__ out) {
    extern __shared__ __align__(128) unsigned char smem[];
    const uint32_t sb = (uint32_t)__cvta_generic_to_shared(smem);
    const int tid = threadIdx.x, warp = tid >> 5, lane = tid & 31;
    const int wm = warp & 1, wn = warp >> 1;   // 2M x 4N warps, warp tile 64x32

    // Grid swizzle: 8-wide n-supercolumns (86 = 10*8 + 6).
    int g = blockIdx.x, mTile, nTile;
    if (g < MTILES * 80) { int sc = g >> 9, loc = g & 511; nTile = sc * 8 + (loc & 7); mTile = loc >> 3; }
    else                 { int loc = g - MTILES * 80; nTile = 80 + loc % 6; mTile = loc / 6; }
    const int mBase = mTile * BM, nBase = nTile * BN;

    // cp.async: A = 128 rows x 8 chunks(16B) = 1024 → 4/thread; B same.
    const __half* gA[4];
    uint32_t sAoff[4];
    const __half* gB[4];
    uint32_t sBoff[4];
    #pragma unroll
    for (int i = 0; i < 4; i++) {
        int c = tid + i * 256;
        int r = c >> 3, s = c & 7;
        gA[i] = xh + (size_t)(mBase + r) * IN_DIM + s * 8;
        sAoff[i] = r * ROWB + s * 16;
        gB[i] = wh + (size_t)(nBase + r) * IN_DIM + s * 8;
        sBoff[i] = A_BYTES + r * ROWB + s * 16;
    }

    auto issue = [&](int kt) {
        const uint32_t base = sb + (uint32_t)(kt % NSTAGE) * STAGE_BYTES;
        const int koff = kt * BKH;
        #pragma unroll
        for (int i = 0; i < 4; i++) cp16(base + sAoff[i], gA[i] + koff);
        #pragma unroll
        for (int i = 0; i < 4; i++) cp16(base + sBoff[i], gB[i] + koff);
        asm volatile("cp.async.commit_group;\n");
    };

    const int mat = lane >> 3, mrow = lane & 7;
    // A warp tile 64 rows: mi in {0..3}; mats: (mat&1)->m+8, (mat>>1)->k half
    const uint32_t aAddr0 = (uint32_t)(wm * 64 + ((mat & 1) << 3) + mrow) * ROWB
                          + ((mat >> 1) << 4);
    // B warp tile 32 rows: nj in {0,1}; mats: (mat>>1)->n+8, (mat&1)->k half
    const uint32_t bAddr0 = A_BYTES
                          + (uint32_t)(wn * 32 + ((mat >> 1) << 3) + mrow) * ROWB
                          + ((mat & 1) << 4);

    float acc[4][4][4];
    #pragma unroll
    for (int i = 0; i < 4; i++)
        #pragma unroll
        for (int j = 0; j < 4; j++)
            #pragma unroll
            for (int k = 0; k < 4; k++) acc[i][j][k] = 0.0f;

    issue(0); issue(1);

    for (int kt = 0; kt < KTILES; ++kt) {
        if (kt < KTILES - 1) { asm volatile("cp.async.wait_group 1;\n"); }
        else                 { asm volatile("cp.async.wait_group 0;\n"); }
        __syncthreads();
        // Stage (kt+2)%3 == (kt-1)%3: its readers (iter kt-1) are all past
        // the barrier above. One sync per k-tile.
        if (kt + 2 < KTILES) issue(kt + 2);

        const uint32_t base = sb + (uint32_t)(kt % NSTAGE) * STAGE_BYTES;

        #pragma unroll
        for (int kk = 0; kk < 4; ++kk) {         // 4 x k16 within 64-half tile
            uint32_t af[4][4], bf[2][4];
            #pragma unroll
            for (int mi = 0; mi < 4; ++mi)
                ldsm_x4(af[mi], base + aAddr0 + mi * (16 * ROWB) + kk * 32);
            #pragma unroll
            for (int nj = 0; nj < 2; ++nj)
                ldsm_x4(bf[nj], base + bAddr0 + nj * (16 * ROWB) + kk * 32);
            #pragma unroll
            for (int mi = 0; mi < 4; ++mi) {
                #pragma unroll
                for (int nj = 0; nj < 2; ++nj) {
                    mma_f16(acc[mi][nj * 2],     af[mi], bf[nj][0], bf[nj][1]);
                    mma_f16(acc[mi][nj * 2 + 1], af[mi], bf[nj][2], bf[nj][3]);
                }
            }
        }
    }

    // Epilogue: warp tile 64x32 at (wm*64, wn*32)
    const int mRow = mBase + wm * 64 + (lane >> 2);
    const int nCol = nBase + wn * 32 + ((lane & 3) << 1);
    #pragma unroll
    for (int mi = 0; mi < 4; ++mi) {
        const int m0 = mRow + mi * 16;
        #pragma unroll
        for (int njh = 0; njh < 4; ++njh) {
            const int n = nCol + njh * 8;
            float2 b2 = *reinterpret_cast<const float2*>(&bias[n]);
            float2 o0 = make_float2(acc[mi][njh][0] + b2.x, acc[mi][njh][1] + b2.y);
            float2 o1 = make_float2(acc[mi][njh][2] + b2.x, acc[mi][njh][3] + b2.y);
            *reinterpret_cast<float2*>(&out[(size_t)m0 * OUT_DIM + n])       = o0;
            *reinterpret_cast<float2*>(&out[(size_t)(m0 + 8) * OUT_DIM + n]) = o1;
        }
    }
}

// ---------------------------------------------------------------------------
// Launch
// ---------------------------------------------------------------------------
extern "C" void kernel_launch(void* const* d_in, const int* in_sizes, int n_in,
                              void* d_out, int out_size) {
    const float *x = nullptr, *weight = nullptr, *Bd = nullptr,
                *Bu = nullptr, *bias = nullptr;
    for (int i = 0; i < n_in; i++) {
        switch (in_sizes[i]) {
            case 33554432: x      = (const float*)d_in[i]; break;  // 8192*4096
            case 45088768: weight = (const float*)d_in[i]; break;  // 11008*4096
            case 2113536:  Bd     = (const float*)d_in[i]; break;  // 11008*192
            case 786432:   Bu     = (const float*)d_in[i]; break;  // 192*4096
            case 11008:    bias   = (const float*)d_in[i]; break;
        }
    }
    if (!x && n_in > 0)      x      = (const float*)d_in[0];
    if (!weight && n_in > 1) weight = (const float*)d_in[1];
    if (!Bd && n_in > 2)     Bd     = (const float*)d_in[2];
    if (!Bu && n_in > 3)     Bu     = (const float*)d_in[3];
    if (!bias && n_in > 4)   bias   = (const float*)d_in[4];

    float *gw;
    __half *gxh, *gwh;
    cudaGetSymbolAddress((void**)&gw,  g_w);
    cudaGetSymbolAddress((void**)&gxh, g_xh);
    cudaGetSymbolAddress((void**)&gwh, g_wh);

    cudaFuncSetAttribute(gemm_delta_fused,
                         cudaFuncAttributeMaxDynamicSharedMemorySize, SMEM_BYTES);
    cudaFuncSetAttribute(gemm_main_fp16,
                         cudaFuncAttributeMaxDynamicSharedMemorySize, MAIN_SMEM);

    // 1) x -> fp16
    cvt_half_kernel<<<(33554432 / 4 + 255) / 256, 256>>>(x, gxh, 33554432 / 4);

    // 2) g_w = weight + Bd@Bu (single fused pass, fp32-equivalent 3xTF32)
    gemm_delta_fused<<<dim3(IN_DIM / 128, OUT_DIM / 128), 256, SMEM_BYTES>>>(
        Bd, Bu, weight, gw, OUT_DIM, IN_DIM, RANK_);

    // 3) fake-quant rows of g_w (fp32 decisions), emit fp16 g_wh
    quant_kernel<<<OUT_DIM, 256>>>(gw, gwh);

    // 4) out = xh @ wh^T + bias (128x128 tiles, 2 CTA/SM, K-chunk 64)
    gemm_main_fp16<<<MTILES * NTILES, 256, MAIN_SMEM>>>(gxh, gwh, bias,
                                                        (float*)d_out);
}

// round 10
// speedup vs baseline: 1.2958x; 1.0348x over previous
#include <cuda_runtime.h>
#include <cuda_fp16.h>
#include <cstdint>
#include <cstddef>

// Problem dims (fixed by the dataset)
#define M_DIM   8192      // 4*2048 rows of x
#define IN_DIM  4096      // K of main GEMM
#define OUT_DIM 11008     // N of main GEMM
#define RANK_   192
#define KPACK   576       // 3 * RANK_  (compensated-product K concat)

// ---------------------------------------------------------------------------
// Scratch (static __device__ arrays — allocation-free per harness rules)
// ---------------------------------------------------------------------------
__device__ __align__(256) float  g_w  [(size_t)OUT_DIM * IN_DIM];  // weight+delta fp32
__device__ __align__(256) __half g_xh [(size_t)M_DIM  * IN_DIM];   // x as fp16
__device__ __align__(256) __half g_wh [(size_t)OUT_DIM * IN_DIM];  // quantized w fp16
__device__ __align__(256) __half g_bdp[(size_t)OUT_DIM * KPACK];   // [Ah|Ah|Al] of 64*Bd
__device__ __align__(256) __half g_bup[(size_t)IN_DIM * KPACK];    // [Bh|Bl|Bh] of 64*Bu, [N,K]

// ---------------------------------------------------------------------------
// x -> fp16
// ---------------------------------------------------------------------------
__global__ void cvt_half_kernel(const float* __restrict__ in,
                                __half* __restrict__ out, int n4) {
    int i = blockIdx.x * 256 + threadIdx.x;
    if (i < n4) {
        float4 v = reinterpret_cast<const float4*>(in)[i];
        __half2 h0 = __floats2half2_rn(v.x, v.y);
        __half2 h1 = __floats2half2_rn(v.z, v.w);
        uint2 p;
        p.x = *reinterpret_cast<uint32_t*>(&h0);
        p.y = *reinterpret_cast<uint32_t*>(&h1);
        reinterpret_cast<uint2*>(out)[i] = p;
    }
}

// ---------------------------------------------------------------------------
// Pack kernels: hi/lo fp16 split of 64*Bd / 64*Bu, K-concatenated so that a
// single fp16 GEMM computes Ah*Bh + Ah*Bl + Al*Bh (= fp32-accurate product;
// dropped Al*Bl ~ 2^-22 rel). Pre-scale x64 keeps lo terms out of deep
// subnormals; the GEMM epilogue divides by 4096.
// ---------------------------------------------------------------------------
__global__ void pack_bd_kernel(const float* __restrict__ bd,
                               __half* __restrict__ out) {
    size_t i = (size_t)blockIdx.x * 256 + threadIdx.x;
    if (i < (size_t)OUT_DIM * KPACK) {
        int o = (int)(i / KPACK), c = (int)(i % KPACK);
        int r = (c < 192) ? c : ((c < 384) ? c - 192 : c - 384);
        float v = bd[(size_t)o * RANK_ + r] * 64.0f;
        __half h = __float2half_rn(v);
        out[i] = (c < 384) ? h : __float2half_rn(v - __half2float(h));
    }
}

// out[n][c]  (pre-transposed to [N,K] so the GEMM B path matches main kernel)
__global__ void pack_bu_kernel(const float* __restrict__ bu,
                               __half* __restrict__ out) {
    size_t i = (size_t)blockIdx.x * 256 + threadIdx.x;
    if (i < (size_t)IN_DIM * KPACK) {
        int n = (int)(i / KPACK), c = (int)(i % KPACK);
        int r = (c < 192) ? c : ((c < 384) ? c - 192 : c - 384);
        float v = bu[(size_t)r * IN_DIM + n] * 64.0f;
        __half h = __float2half_rn(v);
        out[i] = (c < 192 || c >= 384) ? h
                                       : __float2half_rn(v - __half2float(h));
    }
}

// ---------------------------------------------------------------------------
// Row-wise 4-bit asymmetric fake quant: read fp32 g_w once (row cached in
// smem), emit fp16 g_wh.
// ---------------------------------------------------------------------------
__global__ void quant_kernel(const float* __restrict__ w, __half* __restrict__ wh) {
    __shared__ float row[IN_DIM];
    __shared__ float smn[8], smx[8];
    __shared__ float s_scale, s_zero;

    const int rix = blockIdx.x;
    const float* p = w + (size_t)rix * IN_DIM;
    __half* po = wh + (size_t)rix * IN_DIM;
    const int tid = threadIdx.x;

    float mn = 0.0f, mx = 0.0f;   // init 0 implements min/max-with-0 clamp
    #pragma unroll
    for (int i = tid; i < IN_DIM / 4; i += 256) {
        float4 v = reinterpret_cast<const float4*>(p)[i];
        reinterpret_cast<float4*>(row)[i] = v;
        mn = fminf(mn, fminf(fminf(v.x, v.y), fminf(v.z, v.w)));
        mx = fmaxf(mx, fmaxf(fmaxf(v.x, v.y), fmaxf(v.z, v.w)));
    }
    #pragma unroll
    for (int o = 16; o; o >>= 1) {
        mn = fminf(mn, __shfl_xor_sync(0xffffffffu, mn, o));
        mx = fmaxf(mx, __shfl_xor_sync(0xffffffffu, mx, o));
    }
    const int warp = tid >> 5, lane = tid & 31;
    if (lane == 0) { smn[warp] = mn; smx[warp] = mx; }
    __syncthreads();
    if (tid == 0) {
        float a = smn[0], b = smx[0];
        #pragma unroll
        for (int i = 1; i < 8; i++) { a = fminf(a, smn[i]); b = fmaxf(b, smx[i]); }
        float sc = fmaxf((b - a) / 15.0f, 1e-8f);
        s_scale = sc;
        s_zero  = rintf(-a / sc);
    }
    __syncthreads();
    const float sc = s_scale, z = s_zero;

    #pragma unroll
    for (int i = tid; i < IN_DIM / 4; i += 256) {
        float4 v = reinterpret_cast<float4*>(row)[i];
        float q0 = (fminf(fmaxf(rintf(v.x / sc) + z, 0.0f), 15.0f) - z) * sc;
        float q1 = (fminf(fmaxf(rintf(v.y / sc) + z, 0.0f), 15.0f) - z) * sc;
        float q2 = (fminf(fmaxf(rintf(v.z / sc) + z, 0.0f), 15.0f) - z) * sc;
        float q3 = (fminf(fmaxf(rintf(v.w / sc) + z, 0.0f), 15.0f) - z) * sc;
        __half2 h0 = __floats2half2_rn(q0, q1);
        __half2 h1 = __floats2half2_rn(q2, q3);
        uint2 pk;
        pk.x = *reinterpret_cast<uint32_t*>(&h0);
        pk.y = *reinterpret_cast<uint32_t*>(&h1);
        reinterpret_cast<uint2*>(po)[i] = pk;
    }
}

// ---------------------------------------------------------------------------
// Shared GEMM building blocks (fp16 m16n8k16 + ldmatrix + cp.async)
// ---------------------------------------------------------------------------
__device__ __forceinline__ void cp16(uint32_t s, const void* g) {
    asm volatile("cp.async.cg.shared.global [%0], [%1], 16;\n" :: "r"(s), "l"(g));
}
__device__ __forceinline__ void ldsm_x4(uint32_t* r, uint32_t addr) {
    asm volatile("ldmatrix.sync.aligned.m8n8.x4.shared.b16 {%0,%1,%2,%3}, [%4];"
                 : "=r"(r[0]), "=r"(r[1]), "=r"(r[2]), "=r"(r[3]) : "r"(addr));
}
__device__ __forceinline__ void mma_f16(float* d, const uint32_t* a,
                                        uint32_t b0, uint32_t b1) {
    asm volatile(
        "mma.sync.aligned.m16n8k16.row.col.f32.f16.f16.f32 "
        "{%0,%1,%2,%3}, {%4,%5,%6,%7}, {%8,%9}, {%0,%1,%2,%3};\n"
        : "+f"(d[0]), "+f"(d[1]), "+f"(d[2]), "+f"(d[3])
        : "r"(a[0]), "r"(a[1]), "r"(a[2]), "r"(a[3]), "r"(b0), "r"(b1));
}

// Common tile geometry (both GEMMs): CTA 128x128, 256 thr, 2 CTA/SM,
// K-chunk 64 halves, ROWB=144 (128B data + 16B pad), 3-stage cp.async.
#define BM 128
#define BN 128
#define BKH 64
#define ROWB 144
#define A_BYTES (BM * ROWB)               // 18432
#define B_BYTES (BN * ROWB)               // 18432
#define STAGE_BYTES (A_BYTES + B_BYTES)   // 36864
#define NSTAGE 3
#define GEMM_SMEM (NSTAGE * STAGE_BYTES)  // 110592
#define KTILES_MAIN (IN_DIM / BKH)        // 64
#define KTILES_DELTA (KPACK / BKH)        // 9
#define MTILES (M_DIM / BM)               // 64
#define NTILES (OUT_DIM / BN)             // 86

// ---------------------------------------------------------------------------
// Delta GEMM (fp16, K=576): g_w[M=11008, N=4096] =
//     weight + (g_bdp @ g_bup^T) / 4096
// Same structure as the main GEMM; plain 2D grid (B'' is 4.7MB, L2-resident).
// ---------------------------------------------------------------------------
__global__ __launch_bounds__(256, 2)
void gemm_delta_f16(const __half* __restrict__ ap, const __half* __restrict__ bp,
                    const float* __restrict__ wgt, float* __restrict__ outw) {
    extern __shared__ __align__(128) unsigned char smem[];
    const uint32_t sb = (uint32_t)__cvta_generic_to_shared(smem);
    const int tid = threadIdx.x, warp = tid >> 5, lane = tid & 31;
    const int wm = warp & 1, wn = warp >> 1;   // 2M x 4N, warp tile 64x32

    const int mBase = blockIdx.y * BM, nBase = blockIdx.x * BN;

    const __half* gA[4]; uint32_t sAoff[4];
    const __half* gB[4]; uint32_t sBoff[4];
    #pragma unroll
    for (int i = 0; i < 4; i++) {
        int c = tid + i * 256;
        int r = c >> 3, s = c & 7;
        gA[i] = ap + (size_t)(mBase + r) * KPACK + s * 8;
        sAoff[i] = r * ROWB + s * 16;
        gB[i] = bp + (size_t)(nBase + r) * KPACK + s * 8;
        sBoff[i] = A_BYTES + r * ROWB + s * 16;
    }

    auto issue = [&](int kt) {
        const uint32_t base = sb + (uint32_t)(kt % NSTAGE) * STAGE_BYTES;
        const int koff = kt * BKH;
        #pragma unroll
        for (int i = 0; i < 4; i++) cp16(base + sAoff[i], gA[i] + koff);
        #pragma unroll
        for (int i = 0; i < 4; i++) cp16(base + sBoff[i], gB[i] + koff);
        asm volatile("cp.async.commit_group;\n");
    };

    const int mat = lane >> 3, mrow = lane & 7;
    const uint32_t aAddr0 = (uint32_t)(wm * 64 + ((mat & 1) << 3) + mrow) * ROWB
                          + ((mat >> 1) << 4);
    const uint32_t bAddr0 = A_BYTES
                          + (uint32_t)(wn * 32 + ((mat >> 1) << 3) + mrow) * ROWB
                          + ((mat & 1) << 4);

    float acc[4][4][4];
    #pragma unroll
    for (int i = 0; i < 4; i++)
        #pragma unroll
        for (int j = 0; j < 4; j++)
            #pragma unroll
            for (int k = 0; k < 4; k++) acc[i][j][k] = 0.0f;

    issue(0); issue(1);

    for (int kt = 0; kt < KTILES_DELTA; ++kt) {
        if (kt < KTILES_DELTA - 1) { asm volatile("cp.async.wait_group 1;\n"); }
        else                       { asm volatile("cp.async.wait_group 0;\n"); }
        __syncthreads();
        if (kt + 2 < KTILES_DELTA) issue(kt + 2);

        const uint32_t base = sb + (uint32_t)(kt % NSTAGE) * STAGE_BYTES;

        #pragma unroll
        for (int kk = 0; kk < 4; ++kk) {
            uint32_t af[4][4], bf[2][4];
            #pragma unroll
            for (int mi = 0; mi < 4; ++mi)
                ldsm_x4(af[mi], base + aAddr0 + mi * (16 * ROWB) + kk * 32);
            #pragma unroll
            for (int nj = 0; nj < 2; ++nj)
                ldsm_x4(bf[nj], base + bAddr0 + nj * (16 * ROWB) + kk * 32);
            #pragma unroll
            for (int mi = 0; mi < 4; ++mi) {
                #pragma unroll
                for (int nj = 0; nj < 2; ++nj) {
                    mma_f16(acc[mi][nj * 2],     af[mi], bf[nj][0], bf[nj][1]);
                    mma_f16(acc[mi][nj * 2 + 1], af[mi], bf[nj][2], bf[nj][3]);
                }
            }
        }
    }

    // Epilogue: out = acc/4096 + weight (both fp32, N stride = IN_DIM)
    const float SC = 1.0f / 4096.0f;
    const int mRow = mBase + wm * 64 + (lane >> 2);
    const int nCol = nBase + wn * 32 + ((lane & 3) << 1);
    #pragma unroll
    for (int mi = 0; mi < 4; ++mi) {
        const int m0 = mRow + mi * 16;
        #pragma unroll
        for (int njh = 0; njh < 4; ++njh) {
            const int n = nCol + njh * 8;
            float2 w0 = *reinterpret_cast<const float2*>(&wgt[(size_t)m0 * IN_DIM + n]);
            float2 w1 = *reinterpret_cast<const float2*>(&wgt[(size_t)(m0 + 8) * IN_DIM + n]);
            float2 o0 = make_float2(acc[mi][njh][0] * SC + w0.x,
                                    acc[mi][njh][1] * SC + w0.y);
            float2 o1 = make_float2(acc[mi][njh][2] * SC + w1.x,
                                    acc[mi][njh][3] * SC + w1.y);
            *reinterpret_cast<float2*>(&outw[(size_t)m0 * IN_DIM + n])       = o0;
            *reinterpret_cast<float2*>(&outw[(size_t)(m0 + 8) * IN_DIM + n]) = o1;
        }
    }
}

// ---------------------------------------------------------------------------
// Main GEMM: out[8192,11008] = xh[8192,4096] @ wh[11008,4096]^T + bias
// (unchanged from R9: 128x128, 2 CTA/SM, BKH=64, 3-stage, 64 barriers)
// ---------------------------------------------------------------------------
__global__ __launch_bounds__(256, 2)
void gemm_main_fp16(const __half* __restrict__ xh, const __half* __restrict__ wh,
                    const float* __restrict__ bias, float* __restrict__ out) {
    extern __shared__ __align__(128) unsigned char smem[];
    const uint32_t sb = (uint32_t)__cvta_generic_to_shared(smem);
    const int tid = threadIdx.x, warp = tid >> 5, lane = tid & 31;
    const int wm = warp & 1, wn = warp >> 1;   // 2M x 4N warps, warp tile 64x32

    // Grid swizzle: 8-wide n-supercolumns (86 = 10*8 + 6).
    int g = blockIdx.x, mTile, nTile;
    if (g < MTILES * 80) { int sc = g >> 9, loc = g & 511; nTile = sc * 8 + (loc & 7); mTile = loc >> 3; }
    else                 { int loc = g - MTILES * 80; nTile = 80 + loc % 6; mTile = loc / 6; }
    const int mBase = mTile * BM, nBase = nTile * BN;

    const __half* gA[4]; uint32_t sAoff[4];
    const __half* gB[4]; uint32_t sBoff[4];
    #pragma unroll
    for (int i = 0; i < 4; i++) {
        int c = tid + i * 256;
        int r = c >> 3, s = c & 7;
        gA[i] = xh + (size_t)(mBase + r) * IN_DIM + s * 8;
        sAoff[i] = r * ROWB + s * 16;
        gB[i] = wh + (size_t)(nBase + r) * IN_DIM + s * 8;
        sBoff[i] = A_BYTES + r * ROWB + s * 16;
    }

    auto issue = [&](int kt) {
        const uint32_t base = sb + (uint32_t)(kt % NSTAGE) * STAGE_BYTES;
        const int koff = kt * BKH;
        #pragma unroll
        for (int i = 0; i < 4; i++) cp16(base + sAoff[i], gA[i] + koff);
        #pragma unroll
        for (int i = 0; i < 4; i++) cp16(base + sBoff[i], gB[i] + koff);
        asm volatile("cp.async.commit_group;\n");
    };

    const int mat = lane >> 3, mrow = lane & 7;
    const uint32_t aAddr0 = (uint32_t)(wm * 64 + ((mat & 1) << 3) + mrow) * ROWB
                          + ((mat >> 1) << 4);
    const uint32_t bAddr0 = A_BYTES
                          + (uint32_t)(wn * 32 + ((mat >> 1) << 3) + mrow) * ROWB
                          + ((mat & 1) << 4);

    float acc[4][4][4];
    #pragma unroll
    for (int i = 0; i < 4; i++)
        #pragma unroll
        for (int j = 0; j < 4; j++)
            #pragma unroll
            for (int k = 0; k < 4; k++) acc[i][j][k] = 0.0f;

    issue(0); issue(1);

    for (int kt = 0; kt < KTILES_MAIN; ++kt) {
        if (kt < KTILES_MAIN - 1) { asm volatile("cp.async.wait_group 1;\n"); }
        else                      { asm volatile("cp.async.wait_group 0;\n"); }
        __syncthreads();
        if (kt + 2 < KTILES_MAIN) issue(kt + 2);

        const uint32_t base = sb + (uint32_t)(kt % NSTAGE) * STAGE_BYTES;

        #pragma unroll
        for (int kk = 0; kk < 4; ++kk) {
            uint32_t af[4][4], bf[2][4];
            #pragma unroll
            for (int mi = 0; mi < 4; ++mi)
                ldsm_x4(af[mi], base + aAddr0 + mi * (16 * ROWB) + kk * 32);
            #pragma unroll
            for (int nj = 0; nj < 2; ++nj)
                ldsm_x4(bf[nj], base + bAddr0 + nj * (16 * ROWB) + kk * 32);
            #pragma unroll
            for (int mi = 0; mi < 4; ++mi) {
                #pragma unroll
                for (int nj = 0; nj < 2; ++nj) {
                    mma_f16(acc[mi][nj * 2],     af[mi], bf[nj][0], bf[nj][1]);
                    mma_f16(acc[mi][nj * 2 + 1], af[mi], bf[nj][2], bf[nj][3]);
                }
            }
        }
    }

    const int mRow = mBase + wm * 64 + (lane >> 2);
    const int nCol = nBase + wn * 32 + ((lane & 3) << 1);
    #pragma unroll
    for (int mi = 0; mi < 4; ++mi) {
        const int m0 = mRow + mi * 16;
        #pragma unroll
        for (int njh = 0; njh < 4; ++njh) {
            const int n = nCol + njh * 8;
            float2 b2 = *reinterpret_cast<const float2*>(&bias[n]);
            float2 o0 = make_float2(acc[mi][njh][0] + b2.x, acc[mi][njh][1] + b2.y);
            float2 o1 = make_float2(acc[mi][njh][2] + b2.x, acc[mi][njh][3] + b2.y);
            *reinterpret_cast<float2*>(&out[(size_t)m0 * OUT_DIM + n])       = o0;
            *reinterpret_cast<float2*>(&out[(size_t)(m0 + 8) * OUT_DIM + n]) = o1;
        }
    }
}

// ---------------------------------------------------------------------------
// Launch
// ---------------------------------------------------------------------------
extern "C" void kernel_launch(void* const* d_in, const int* in_sizes, int n_in,
                              void* d_out, int out_size) {
    const float *x = nullptr, *weight = nullptr, *Bd = nullptr,
                *Bu = nullptr, *bias = nullptr;
    for (int i = 0; i < n_in; i++) {
        switch (in_sizes[i]) {
            case 33554432: x      = (const float*)d_in[i]; break;  // 8192*4096
            case 45088768: weight = (const float*)d_in[i]; break;  // 11008*4096
            case 2113536:  Bd     = (const float*)d_in[i]; break;  // 11008*192
            case 786432:   Bu     = (const float*)d_in[i]; break;  // 192*4096
            case 11008:    bias   = (const float*)d_in[i]; break;
        }
    }
    if (!x && n_in > 0)      x      = (const float*)d_in[0];
    if (!weight && n_in > 1) weight = (const float*)d_in[1];
    if (!Bd && n_in > 2)     Bd     = (const float*)d_in[2];
    if (!Bu && n_in > 3)     Bu     = (const float*)d_in[3];
    if (!bias && n_in > 4)   bias   = (const float*)d_in[4];

    float *gw;
    __half *gxh, *gwh, *gbdp, *gbup;
    cudaGetSymbolAddress((void**)&gw,   g_w);
    cudaGetSymbolAddress((void**)&gxh,  g_xh);
    cudaGetSymbolAddress((void**)&gwh,  g_wh);
    cudaGetSymbolAddress((void**)&gbdp, g_bdp);
    cudaGetSymbolAddress((void**)&gbup, g_bup);

    cudaFuncSetAttribute(gemm_delta_f16,
                         cudaFuncAttributeMaxDynamicSharedMemorySize, GEMM_SMEM);
    cudaFuncSetAttribute(gemm_main_fp16,
                         cudaFuncAttributeMaxDynamicSharedMemorySize, GEMM_SMEM);

    // 1) x -> fp16;  Bd/Bu -> packed hi/lo fp16 (K=576 concat, x64 scaled)
    cvt_half_kernel<<<(33554432 / 4 + 255) / 256, 256>>>(x, gxh, 33554432 / 4);
    pack_bd_kernel<<<((size_t)OUT_DIM * KPACK + 255) / 256, 256>>>(Bd, gbdp);
    pack_bu_kernel<<<((size_t)IN_DIM * KPACK + 255) / 256, 256>>>(Bu, gbup);

    // 2) g_w = weight + Bd@Bu / ... via single fp16 GEMM (K=576)
    gemm_delta_f16<<<dim3(IN_DIM / BN, OUT_DIM / BM), 256, GEMM_SMEM>>>(
        gbdp, gbup, weight, gw);

    // 3) fake-quant rows of g_w (fp32 decisions, single pass), emit fp16 g_wh
    quant_kernel<<<OUT_DIM, 256>>>(gw, gwh);

    // 4) out = xh @ wh^T + bias (128x128 tiles, 2 CTA/SM, K-chunk 64)
    gemm_main_fp16<<<MTILES * NTILES, 256, GEMM_SMEM>>>(gxh, gwh, bias,
                                                        (float*)d_out);
}

// round 11
// speedup vs baseline: 1.3035x; 1.0059x over previous
#include <cuda_runtime.h>
#include <cuda_fp16.h>
#include <cstdint>
#include <cstddef>

// Problem dims (fixed by the dataset)
#define M_DIM   8192      // 4*2048 rows of x
#define IN_DIM  4096      // K of main GEMM
#define OUT_DIM 11008     // N of main GEMM
#define RANK_   192
#define KPACK   576       // 3 * RANK_  (compensated-product K concat)

// ---------------------------------------------------------------------------
// Scratch (static __device__ arrays — allocation-free per harness rules)
// ---------------------------------------------------------------------------
__device__ __align__(256) float  g_w  [(size_t)OUT_DIM * IN_DIM];  // weight+delta fp32
__device__ __align__(256) __half g_xh [(size_t)M_DIM  * IN_DIM];   // x as fp16
__device__ __align__(256) __half g_wh [(size_t)OUT_DIM * IN_DIM];  // quantized w fp16
__device__ __align__(256) __half g_bdp[(size_t)OUT_DIM * KPACK];   // [Ah|Ah|Al] of 64*Bd
__device__ __align__(256) __half g_bup[(size_t)IN_DIM * KPACK];    // [Bh|Bl|Bh] of 64*Bu, [N,K]

// ---------------------------------------------------------------------------
// x -> fp16
// ---------------------------------------------------------------------------
__global__ void cvt_half_kernel(const float* __restrict__ in,
                                __half* __restrict__ out, int n4) {
    int i = blockIdx.x * 256 + threadIdx.x;
    if (i < n4) {
        float4 v = reinterpret_cast<const float4*>(in)[i];
        __half2 h0 = __floats2half2_rn(v.x, v.y);
        __half2 h1 = __floats2half2_rn(v.z, v.w);
        uint2 p;
        p.x = *reinterpret_cast<uint32_t*>(&h0);
        p.y = *reinterpret_cast<uint32_t*>(&h1);
        reinterpret_cast<uint2*>(out)[i] = p;
    }
}

// ---------------------------------------------------------------------------
// Pack kernels: hi/lo fp16 split of 64*Bd / 64*Bu, K-concatenated so that a
// single fp16 GEMM computes Ah*Bh + Ah*Bl + Al*Bh (= fp32-accurate product;
// dropped Al*Bl ~ 2^-22 rel). Pre-scale x64 keeps lo terms out of deep
// subnormals; the GEMM epilogue divides by 4096.
// ---------------------------------------------------------------------------
__global__ void pack_bd_kernel(const float* __restrict__ bd,
                               __half* __restrict__ out) {
    size_t i = (size_t)blockIdx.x * 256 + threadIdx.x;
    if (i < (size_t)OUT_DIM * KPACK) {
        int o = (int)(i / KPACK), c = (int)(i % KPACK);
        int r = (c < 192) ? c : ((c < 384) ? c - 192 : c - 384);
        float v = bd[(size_t)o * RANK_ + r] * 64.0f;
        __half h = __float2half_rn(v);
        out[i] = (c < 384) ? h : __float2half_rn(v - __half2float(h));
    }
}

// out[n][c]  (pre-transposed to [N,K] so the GEMM B path matches main kernel)
__global__ void pack_bu_kernel(const float* __restrict__ bu,
                               __half* __restrict__ out) {
    size_t i = (size_t)blockIdx.x * 256 + threadIdx.x;
    if (i < (size_t)IN_DIM * KPACK) {
        int n = (int)(i / KPACK), c = (int)(i % KPACK);
        int r = (c < 192) ? c : ((c < 384) ? c - 192 : c - 384);
        float v = bu[(size_t)r * IN_DIM + n] * 64.0f;
        __half h = __float2half_rn(v);
        out[i] = (c < 192 || c >= 384) ? h
                                       : __float2half_rn(v - __half2float(h));
    }
}

// ---------------------------------------------------------------------------
// Row-wise 4-bit asymmetric fake quant: read fp32 g_w once (row cached in
// smem), emit fp16 g_wh.
// ---------------------------------------------------------------------------
__global__ void quant_kernel(const float* __restrict__ w, __half* __restrict__ wh) {
    __shared__ float row[IN_DIM];
    __shared__ float smn[8], smx[8];
    __shared__ float s_scale, s_zero;

    const int rix = blockIdx.x;
    const float* p = w + (size_t)rix * IN_DIM;
    __half* po = wh + (size_t)rix * IN_DIM;
    const int tid = threadIdx.x;

    float mn = 0.0f, mx = 0.0f;   // init 0 implements min/max-with-0 clamp
    #pragma unroll
    for (int i = tid; i < IN_DIM / 4; i += 256) {
        float4 v = reinterpret_cast<const float4*>(p)[i];
        reinterpret_cast<float4*>(row)[i] = v;
        mn = fminf(mn, fminf(fminf(v.x, v.y), fminf(v.z, v.w)));
        mx = fmaxf(mx, fmaxf(fmaxf(v.x, v.y), fmaxf(v.z, v.w)));
    }
    #pragma unroll
    for (int o = 16; o; o >>= 1) {
        mn = fminf(mn, __shfl_xor_sync(0xffffffffu, mn, o));
        mx = fmaxf(mx, __shfl_xor_sync(0xffffffffu, mx, o));
    }
    const int warp = tid >> 5, lane = tid & 31;
    if (lane == 0) { smn[warp] = mn; smx[warp] = mx; }
    __syncthreads();
    if (tid == 0) {
        float a = smn[0], b = smx[0];
        #pragma unroll
        for (int i = 1; i < 8; i++) { a = fminf(a, smn[i]); b = fmaxf(b, smx[i]); }
        float sc = fmaxf((b - a) / 15.0f, 1e-8f);
        s_scale = sc;
        s_zero  = rintf(-a / sc);
    }
    __syncthreads();
    const float sc = s_scale, z = s_zero;

    #pragma unroll
    for (int i = tid; i < IN_DIM / 4; i += 256) {
        float4 v = reinterpret_cast<float4*>(row)[i];
        float q0 = (fminf(fmaxf(rintf(v.x / sc) + z, 0.0f), 15.0f) - z) * sc;
        float q1 = (fminf(fmaxf(rintf(v.y / sc) + z, 0.0f), 15.0f) - z) * sc;
        float q2 = (fminf(fmaxf(rintf(v.z / sc) + z, 0.0f), 15.0f) - z) * sc;
        float q3 = (fminf(fmaxf(rintf(v.w / sc) + z, 0.0f), 15.0f) - z) * sc;
        __half2 h0 = __floats2half2_rn(q0, q1);
        __half2 h1 = __floats2half2_rn(q2, q3);
        uint2 pk;
        pk.x = *reinterpret_cast<uint32_t*>(&h0);
        pk.y = *reinterpret_cast<uint32_t*>(&h1);
        reinterpret_cast<uint2*>(po)[i] = pk;
    }
}

// ---------------------------------------------------------------------------
// Shared GEMM building blocks (fp16 m16n8k16 + ldmatrix + cp.async)
// ---------------------------------------------------------------------------
__device__ __forceinline__ void cp16(uint32_t s, const void* g) {
    asm volatile("cp.async.cg.shared.global [%0], [%1], 16;\n" :: "r"(s), "l"(g));
}
__device__ __forceinline__ void ldsm_x4(uint32_t* r, uint32_t addr) {
    asm volatile("ldmatrix.sync.aligned.m8n8.x4.shared.b16 {%0,%1,%2,%3}, [%4];"
                 : "=r"(r[0]), "=r"(r[1]), "=r"(r[2]), "=r"(r[3]) : "r"(addr));
}
__device__ __forceinline__ void mma_f16(float* d, const uint32_t* a,
                                        uint32_t b0, uint32_t b1) {
    asm volatile(
        "mma.sync.aligned.m16n8k16.row.col.f32.f16.f16.f32 "
        "{%0,%1,%2,%3}, {%4,%5,%6,%7}, {%8,%9}, {%0,%1,%2,%3};\n"
        : "+f"(d[0]), "+f"(d[1]), "+f"(d[2]), "+f"(d[3])
        : "r"(a[0]), "r"(a[1]), "r"(a[2]), "r"(a[3]), "r"(b0), "r"(b1));
}

// Common tile geometry (both GEMMs): CTA 128x128, 256 thr, 2 CTA/SM,
// K-chunk 64 halves, ROWB=144 (128B data + 16B pad), 3-stage cp.async.
#define BM 128
#define BN 128
#define BKH 64
#define ROWB 144
#define A_BYTES (BM * ROWB)               // 18432
#define B_BYTES (BN * ROWB)               // 18432
#define STAGE_BYTES (A_BYTES + B_BYTES)   // 36864
#define NSTAGE 3
#define GEMM_SMEM (NSTAGE * STAGE_BYTES)  // 110592
#define KTILES_MAIN (IN_DIM / BKH)        // 64
#define KTILES_DELTA (KPACK / BKH)        // 9
#define MTILES (M_DIM / BM)               // 64
#define NTILES (OUT_DIM / BN)             // 86
#define EPI_STRIDE 136                    // floats; row bank-shift 8 => conflict-free

// ---------------------------------------------------------------------------
// Delta GEMM (fp16, K=576): g_w[M=11008, N=4096] =
//     weight + (g_bdp @ g_bup^T) / 4096
// R11: epilogue stages the 128x128 fp32 tile through smem so weight reads
// and g_w writes are fully coalesced float4 streams.
// ---------------------------------------------------------------------------
__global__ __launch_bounds__(256, 2)
void gemm_delta_f16(const __half* __restrict__ ap, const __half* __restrict__ bp,
                    const float* __restrict__ wgt, float* __restrict__ outw) {
    extern __shared__ __align__(128) unsigned char smem[];
    const uint32_t sb = (uint32_t)__cvta_generic_to_shared(smem);
    const int tid = threadIdx.x, warp = tid >> 5, lane = tid & 31;
    const int wm = warp & 1, wn = warp >> 1;   // 2M x 4N, warp tile 64x32

    const int mBase = blockIdx.y * BM, nBase = blockIdx.x * BN;

    const __half* gA[4]; uint32_t sAoff[4];
    const __half* gB[4]; uint32_t sBoff[4];
    #pragma unroll
    for (int i = 0; i < 4; i++) {
        int c = tid + i * 256;
        int r = c >> 3, s = c & 7;
        gA[i] = ap + (size_t)(mBase + r) * KPACK + s * 8;
        sAoff[i] = r * ROWB + s * 16;
        gB[i] = bp + (size_t)(nBase + r) * KPACK + s * 8;
        sBoff[i] = A_BYTES + r * ROWB + s * 16;
    }

    auto issue = [&](int kt) {
        const uint32_t base = sb + (uint32_t)(kt % NSTAGE) * STAGE_BYTES;
        const int koff = kt * BKH;
        #pragma unroll
        for (int i = 0; i < 4; i++) cp16(base + sAoff[i], gA[i] + koff);
        #pragma unroll
        for (int i = 0; i < 4; i++) cp16(base + sBoff[i], gB[i] + koff);
        asm volatile("cp.async.commit_group;\n");
    };

    const int mat = lane >> 3, mrow = lane & 7;
    const uint32_t aAddr0 = (uint32_t)(wm * 64 + ((mat & 1) << 3) + mrow) * ROWB
                          + ((mat >> 1) << 4);
    const uint32_t bAddr0 = A_BYTES
                          + (uint32_t)(wn * 32 + ((mat >> 1) << 3) + mrow) * ROWB
                          + ((mat & 1) << 4);

    float acc[4][4][4];
    #pragma unroll
    for (int i = 0; i < 4; i++)
        #pragma unroll
        for (int j = 0; j < 4; j++)
            #pragma unroll
            for (int k = 0; k < 4; k++) acc[i][j][k] = 0.0f;

    issue(0); issue(1);

    for (int kt = 0; kt < KTILES_DELTA; ++kt) {
        if (kt < KTILES_DELTA - 1) { asm volatile("cp.async.wait_group 1;\n"); }
        else                       { asm volatile("cp.async.wait_group 0;\n"); }
        __syncthreads();
        if (kt + 2 < KTILES_DELTA) issue(kt + 2);

        const uint32_t base = sb + (uint32_t)(kt % NSTAGE) * STAGE_BYTES;

        #pragma unroll
        for (int kk = 0; kk < 4; ++kk) {
            uint32_t af[4][4], bf[2][4];
            #pragma unroll
            for (int mi = 0; mi < 4; ++mi)
                ldsm_x4(af[mi], base + aAddr0 + mi * (16 * ROWB) + kk * 32);
            #pragma unroll
            for (int nj = 0; nj < 2; ++nj)
                ldsm_x4(bf[nj], base + bAddr0 + nj * (16 * ROWB) + kk * 32);
            #pragma unroll
            for (int mi = 0; mi < 4; ++mi) {
                #pragma unroll
                for (int nj = 0; nj < 2; ++nj) {
                    mma_f16(acc[mi][nj * 2],     af[mi], bf[nj][0], bf[nj][1]);
                    mma_f16(acc[mi][nj * 2 + 1], af[mi], bf[nj][2], bf[nj][3]);
                }
            }
        }
    }

    // Epilogue via smem staging: scatter acc -> smem (conflict-free), then
    // stream coalesced float4: out = acc/4096 + weight.
    __syncthreads();   // all warps done reading pipeline stages
    float* st = reinterpret_cast<float*>(smem);
    {
        const int mr = wm * 64 + (lane >> 2);
        const int nc = wn * 32 + ((lane & 3) << 1);
        #pragma unroll
        for (int mi = 0; mi < 4; ++mi) {
            const int m0 = mr + mi * 16;
            #pragma unroll
            for (int njh = 0; njh < 4; ++njh) {
                const int n = nc + njh * 8;
                st[m0 * EPI_STRIDE + n]           = acc[mi][njh][0];
                st[m0 * EPI_STRIDE + n + 1]       = acc[mi][njh][1];
                st[(m0 + 8) * EPI_STRIDE + n]     = acc[mi][njh][2];
                st[(m0 + 8) * EPI_STRIDE + n + 1] = acc[mi][njh][3];
            }
        }
    }
    __syncthreads();
    const float SC = 1.0f / 4096.0f;
    #pragma unroll
    for (int it = 0; it < 16; ++it) {
        int i = tid + it * 256;                  // 0..4095 float4 slots
        int row = i >> 5, c4 = i & 31;
        float4 v = *reinterpret_cast<float4*>(&st[row * EPI_STRIDE + c4 * 4]);
        size_t gofs = (size_t)(mBase + row) * IN_DIM + nBase + c4 * 4;
        float4 w4 = *reinterpret_cast<const float4*>(&wgt[gofs]);
        v.x = v.x * SC + w4.x;
        v.y = v.y * SC + w4.y;
        v.z = v.z * SC + w4.z;
        v.w = v.w * SC + w4.w;
        *reinterpret_cast<float4*>(&outw[gofs]) = v;
    }
}

// ---------------------------------------------------------------------------
// Main GEMM: out[8192,11008] = xh[8192,4096] @ wh[11008,4096]^T + bias
// (unchanged from R9: 128x128, 2 CTA/SM, BKH=64, 3-stage, 64 barriers)
// ---------------------------------------------------------------------------
__global__ __launch_bounds__(256, 2)
void gemm_main_fp16(const __half* __restrict__ xh, const __half* __restrict__ wh,
                    const float* __restrict__ bias, float* __restrict__ out) {
    extern __shared__ __align__(128) unsigned char smem[];
    const uint32_t sb = (uint32_t)__cvta_generic_to_shared(smem);
    const int tid = threadIdx.x, warp = tid >> 5, lane = tid & 31;
    const int wm = warp & 1, wn = warp >> 1;   // 2M x 4N warps, warp tile 64x32

    // Grid swizzle: 8-wide n-supercolumns (86 = 10*8 + 6).
    int g = blockIdx.x, mTile, nTile;
    if (g < MTILES * 80) { int sc = g >> 9, loc = g & 511; nTile = sc * 8 + (loc & 7); mTile = loc >> 3; }
    else                 { int loc = g - MTILES * 80; nTile = 80 + loc % 6; mTile = loc / 6; }
    const int mBase = mTile * BM, nBase = nTile * BN;

    const __half* gA[4]; uint32_t sAoff[4];
    const __half* gB[4]; uint32_t sBoff[4];
    #pragma unroll
    for (int i = 0; i < 4; i++) {
        int c = tid + i * 256;
        int r = c >> 3, s = c & 7;
        gA[i] = xh + (size_t)(mBase + r) * IN_DIM + s * 8;
        sAoff[i] = r * ROWB + s * 16;
        gB[i] = wh + (size_t)(nBase + r) * IN_DIM + s * 8;
        sBoff[i] = A_BYTES + r * ROWB + s * 16;
    }

    auto issue = [&](int kt) {
        const uint32_t base = sb + (uint32_t)(kt % NSTAGE) * STAGE_BYTES;
        const int koff = kt * BKH;
        #pragma unroll
        for (int i = 0; i < 4; i++) cp16(base + sAoff[i], gA[i] + koff);
        #pragma unroll
        for (int i = 0; i < 4; i++) cp16(base + sBoff[i], gB[i] + koff);
        asm volatile("cp.async.commit_group;\n");
    };

    const int mat = lane >> 3, mrow = lane & 7;
    const uint32_t aAddr0 = (uint32_t)(wm * 64 + ((mat & 1) << 3) + mrow) * ROWB
                          + ((mat >> 1) << 4);
    const uint32_t bAddr0 = A_BYTES
                          + (uint32_t)(wn * 32 + ((mat >> 1) << 3) + mrow) * ROWB
                          + ((mat & 1) << 4);

    float acc[4][4][4];
    #pragma unroll
    for (int i = 0; i < 4; i++)
        #pragma unroll
        for (int j = 0; j < 4; j++)
            #pragma unroll
            for (int k = 0; k < 4; k++) acc[i][j][k] = 0.0f;

    issue(0); issue(1);

    for (int kt = 0; kt < KTILES_MAIN; ++kt) {
        if (kt < KTILES_MAIN - 1) { asm volatile("cp.async.wait_group 1;\n"); }
        else                      { asm volatile("cp.async.wait_group 0;\n"); }
        __syncthreads();
        if (kt + 2 < KTILES_MAIN) issue(kt + 2);

        const uint32_t base = sb + (uint32_t)(kt % NSTAGE) * STAGE_BYTES;

        #pragma unroll
        for (int kk = 0; kk < 4; ++kk) {
            uint32_t af[4][4], bf[2][4];
            #pragma unroll
            for (int mi = 0; mi < 4; ++mi)
                ldsm_x4(af[mi], base + aAddr0 + mi * (16 * ROWB) + kk * 32);
            #pragma unroll
            for (int nj = 0; nj < 2; ++nj)
                ldsm_x4(bf[nj], base + bAddr0 + nj * (16 * ROWB) + kk * 32);
            #pragma unroll
            for (int mi = 0; mi < 4; ++mi) {
                #pragma unroll
                for (int nj = 0; nj < 2; ++nj) {
                    mma_f16(acc[mi][nj * 2],     af[mi], bf[nj][0], bf[nj][1]);
                    mma_f16(acc[mi][nj * 2 + 1], af[mi], bf[nj][2], bf[nj][3]);
                }
            }
        }
    }

    const int mRow = mBase + wm * 64 + (lane >> 2);
    const int nCol = nBase + wn * 32 + ((lane & 3) << 1);
    #pragma unroll
    for (int mi = 0; mi < 4; ++mi) {
        const int m0 = mRow + mi * 16;
        #pragma unroll
        for (int njh = 0; njh < 4; ++njh) {
            const int n = nCol + njh * 8;
            float2 b2 = *reinterpret_cast<const float2*>(&bias[n]);
            float2 o0 = make_float2(acc[mi][njh][0] + b2.x, acc[mi][njh][1] + b2.y);
            float2 o1 = make_float2(acc[mi][njh][2] + b2.x, acc[mi][njh][3] + b2.y);
            *reinterpret_cast<float2*>(&out[(size_t)m0 * OUT_DIM + n])       = o0;
            *reinterpret_cast<float2*>(&out[(size_t)(m0 + 8) * OUT_DIM + n]) = o1;
        }
    }
}

// ---------------------------------------------------------------------------
// Launch
// ---------------------------------------------------------------------------
extern "C" void kernel_launch(void* const* d_in, const int* in_sizes, int n_in,
                              void* d_out, int out_size) {
    const float *x = nullptr, *weight = nullptr, *Bd = nullptr,
                *Bu = nullptr, *bias = nullptr;
    for (int i = 0; i < n_in; i++) {
        switch (in_sizes[i]) {
            case 33554432: x      = (const float*)d_in[i]; break;  // 8192*4096
            case 45088768: weight = (const float*)d_in[i]; break;  // 11008*4096
            case 2113536:  Bd     = (const float*)d_in[i]; break;  // 11008*192
            case 786432:   Bu     = (const float*)d_in[i]; break;  // 192*4096
            case 11008:    bias   = (const float*)d_in[i]; break;
        }
    }
    if (!x && n_in > 0)      x      = (const float*)d_in[0];
    if (!weight && n_in > 1) weight = (const float*)d_in[1];
    if (!Bd && n_in > 2)     Bd     = (const float*)d_in[2];
    if (!Bu && n_in > 3)     Bu     = (const float*)d_in[3];
    if (!bias && n_in > 4)   bias   = (const float*)d_in[4];

    float *gw;
    __half *gxh, *gwh, *gbdp, *gbup;
    cudaGetSymbolAddress((void**)&gw,   g_w);
    cudaGetSymbolAddress((void**)&gxh,  g_xh);
    cudaGetSymbolAddress((void**)&gwh,  g_wh);
    cudaGetSymbolAddress((void**)&gbdp, g_bdp);
    cudaGetSymbolAddress((void**)&gbup, g_bup);

    cudaFuncSetAttribute(gemm_delta_f16,
                         cudaFuncAttributeMaxDynamicSharedMemorySize, GEMM_SMEM);
    cudaFuncSetAttribute(gemm_main_fp16,
                         cudaFuncAttributeMaxDynamicSharedMemorySize, GEMM_SMEM);

    // 1) x -> fp16;  Bd/Bu -> packed hi/lo fp16 (K=576 concat, x64 scaled)
    cvt_half_kernel<<<(33554432 / 4 + 255) / 256, 256>>>(x, gxh, 33554432 / 4);
    pack_bd_kernel<<<((size_t)OUT_DIM * KPACK + 255) / 256, 256>>>(Bd, gbdp);
    pack_bu_kernel<<<((size_t)IN_DIM * KPACK + 255) / 256, 256>>>(Bu, gbup);

    // 2) g_w = weight + Bd@Bu via single fp16 GEMM (K=576, coalesced epilogue)
    gemm_delta_f16<<<dim3(IN_DIM / BN, OUT_DIM / BM), 256, GEMM_SMEM>>>(
        gbdp, gbup, weight, gw);

    // 3) fake-quant rows of g_w (fp32 decisions, single pass), emit fp16 g_wh
    quant_kernel<<<OUT_DIM, 256>>>(gw, gwh);

    // 4) out = xh @ wh^T + bias (128x128 tiles, 2 CTA/SM, K-chunk 64)
    gemm_main_fp16<<<MTILES * NTILES, 256, GEMM_SMEM>>>(gxh, gwh, bias,
                                                        (float*)d_out);
}